// round 10
// baseline (speedup 1.0000x reference)
#include <cuda_runtime.h>
#include <cuda_bf16.h>
#include <cstdint>
#include <cstddef>

#define H_DIM 2560
#define S_DIM 256
#define E_DIM 10
#define V_DIM 50257
#define VPAD  50432            // 197*256 (qb row padding)
#define LDE   50304            // padded expl stride = 393*128
#define R_DIM (S_DIM*E_DIM)    // 2560

// ---------------- scratch (static device allocations) -----------------------
__device__ float g_h[S_DIM*H_DIM];
__device__ float g_eh[(size_t)R_DIM*H_DIM];                // GEMM1 out, fp32
__device__ signed char g_qa[(size_t)R_DIM*H_DIM];          // eh quantized s8
__device__ float g_sa[R_DIM];                              // per-row scale of A
__device__ signed char g_qb[(size_t)VPAD*H_DIM];           // embedding s8, padded
__device__ float g_sb[VPAD];                               // per-row scale of B
__device__ float g_expl[(size_t)R_DIM*LDE];                // exp(logits)
__device__ float g_Z[R_DIM];                               // row sums (atomic)
__device__ float g_gate[S_DIM*E_DIM];

__device__ __forceinline__ float tf32_rna(float x){
    uint32_t u; asm("cvt.rna.tf32.f32 %0, %1;" : "=r"(u) : "f"(x));
    return __uint_as_float(u);
}

__device__ __forceinline__ void cp16(uint32_t d, const void* s){
    asm volatile("cp.async.cg.shared.global [%0], [%1], 16;\n" :: "r"(d), "l"(s));
}
__device__ __forceinline__ void cp_commit(){ asm volatile("cp.async.commit_group;\n"); }

// ---------------- kernel 1: rmsnorm + gate softmax ---------------------------
__global__ void prep_kernel(const float* __restrict__ hid,
                            const float* __restrict__ nscale,
                            const float* __restrict__ gateW){
    int s = blockIdx.x, t = threadIdx.x;
    __shared__ float red[256];
    __shared__ float gred[E_DIM][256];
    float x[10];
    float ss = 0.f;
#pragma unroll
    for (int j=0;j<10;j++){ x[j] = hid[s*H_DIM + t + j*256]; ss += x[j]*x[j]; }
    red[t] = ss; __syncthreads();
    for (int off=128; off; off>>=1){ if(t<off) red[t]+=red[t+off]; __syncthreads(); }
    float inv = rsqrtf(red[0]/(float)H_DIM + 1e-5f);
    float ga[E_DIM];
#pragma unroll
    for(int e=0;e<E_DIM;e++) ga[e]=0.f;
#pragma unroll
    for (int j=0;j<10;j++){
        int i = t + j*256;
        float h = x[j]*inv*nscale[i];
        g_h[s*H_DIM + i] = tf32_rna(h);
#pragma unroll
        for(int e=0;e<E_DIM;e++) ga[e] += h*gateW[i*E_DIM + e];
    }
#pragma unroll
    for(int e=0;e<E_DIM;e++) gred[e][t]=ga[e];
    __syncthreads();
    for(int off=128; off; off>>=1){
        if(t<off){
#pragma unroll
            for(int e=0;e<E_DIM;e++) gred[e][t]+=gred[e][t+off];
        }
        __syncthreads();
    }
    if (t==0){
        float m=-1e30f;
#pragma unroll
        for(int e=0;e<E_DIM;e++) m=fmaxf(m,gred[e][0]);
        float sum=0.f; float ex[E_DIM];
#pragma unroll
        for(int e=0;e<E_DIM;e++){ ex[e]=expf(gred[e][0]-m); sum+=ex[e]; }
#pragma unroll
        for(int e=0;e<E_DIM;e++) g_gate[s*E_DIM+e]=ex[e]/sum;
    }
}

__global__ void zeroZ_kernel(){
    int i = blockIdx.x*256 + threadIdx.x;
    if (i < R_DIM) g_Z[i] = 0.f;
}

// ---------------- per-row s8 quantization ------------------------------------
// One block per row: pass1 max|x|, pass2 quantize with round-to-nearest.
__device__ __forceinline__ void quant_row(const float* __restrict__ src,
                                          signed char* __restrict__ dst,
                                          float* __restrict__ scale_out, int t){
    __shared__ float red[256];
    float mx = 0.f;
    const float4* s4 = (const float4*)src;
    for (int i=t; i<H_DIM/4; i+=256){
        float4 v = s4[i];
        mx = fmaxf(mx, fmaxf(fmaxf(fabsf(v.x),fabsf(v.y)), fmaxf(fabsf(v.z),fabsf(v.w))));
    }
    red[t]=mx; __syncthreads();
    for(int off=128;off;off>>=1){ if(t<off) red[t]=fmaxf(red[t],red[t+off]); __syncthreads(); }
    float m = red[0];
    float inv = (m > 0.f) ? 127.f/m : 0.f;
    char4* d4 = (char4*)dst;
    for (int i=t; i<H_DIM/4; i+=256){
        float4 v = s4[i];
        char4 q;
        q.x = (signed char)max(-127, min(127, __float2int_rn(v.x*inv)));
        q.y = (signed char)max(-127, min(127, __float2int_rn(v.y*inv)));
        q.z = (signed char)max(-127, min(127, __float2int_rn(v.z*inv)));
        q.w = (signed char)max(-127, min(127, __float2int_rn(v.w*inv)));
        d4[i] = q;
    }
    if (t==0) *scale_out = m/127.f;
}

__global__ void quantA_kernel(){
    int r = blockIdx.x;
    quant_row(g_eh + (size_t)r*H_DIM, g_qa + (size_t)r*H_DIM, &g_sa[r], threadIdx.x);
}

__global__ void quantB_kernel(const float* __restrict__ emb){
    int r = blockIdx.x, t = threadIdx.x;
    if (r < V_DIM){
        quant_row(emb + (size_t)r*H_DIM, g_qb + (size_t)r*H_DIM, &g_sb[r], t);
    } else {
        char4* d4 = (char4*)(g_qb + (size_t)r*H_DIM);
        for (int i=t; i<H_DIM/4; i+=256) d4[i] = make_char4(0,0,0,0);
        if (t==0) g_sb[r] = 0.f;
    }
}

// ---------------- GEMM1: legacy tf32 mma, fp32 output ------------------------
#define TM 256
#define TN 128
#define TK 32
#define STAGES 3
#define A_ST 36
#define B_ST_N 132
#define A_FL (TM*A_ST)
#define B_FL (TN*36)
#define STAGE_FL (A_FL + B_FL)
#define SMEM1_BYTES (STAGE_FL*STAGES*4)

__device__ __forceinline__ void mma_tf32(float c[4], uint32_t a0,uint32_t a1,uint32_t a2,uint32_t a3,
                                         uint32_t b0,uint32_t b1){
    asm volatile("mma.sync.aligned.m16n8k8.row.col.f32.tf32.tf32.f32 "
        "{%0,%1,%2,%3},{%4,%5,%6,%7},{%8,%9},{%0,%1,%2,%3};\n"
        : "+f"(c[0]),"+f"(c[1]),"+f"(c[2]),"+f"(c[3])
        : "r"(a0),"r"(a1),"r"(a2),"r"(a3),"r"(b0),"r"(b1));
}

__global__ __launch_bounds__(256)
void gemm1_tf32_kernel(const float* __restrict__ A, const float* __restrict__ Bg,
                       float* __restrict__ C,
                       int K, int ldA, int ldB, int ldC)
{
    extern __shared__ float smem[];
    const int tid = threadIdx.x;
    const int mBase = blockIdx.x*TM, nBase = blockIdx.y*TN;
    const int z = blockIdx.z;
    const float* B = Bg + (size_t)z*(size_t)H_DIM*H_DIM;
    const uint32_t sbase = (uint32_t)__cvta_generic_to_shared(smem);
    const int KT = K/TK;

    auto issue = [&](int kt, int st){
        uint32_t sA = sbase + (uint32_t)(st*STAGE_FL)*4u;
        uint32_t sB = sA + (uint32_t)A_FL*4u;
#pragma unroll
        for (int i=0;i<8;i++){
            int c = tid + i*256;
            int row = c>>3, kc=(c&7)*4;
            cp16(sA + (uint32_t)(row*A_ST+kc)*4u,
                 A + (size_t)(mBase+row)*ldA + kt*TK + kc);
        }
#pragma unroll
        for (int i=0;i<4;i++){
            int c = tid + i*256;
            int k=c>>5, nc=(c&31)*4;
            cp16(sB + (uint32_t)(k*B_ST_N+nc)*4u,
                 B + (size_t)(kt*TK+k)*ldB + nBase + nc);
        }
    };

    issue(0,0); cp_commit();
    issue(1,1); cp_commit();

    const int warp = tid>>5, lane = tid&31;
    const int wm = warp & 3, wn = warp >> 2;
    const int gid = lane>>2, t4 = lane&3;

    float acc[4][8][4];
#pragma unroll
    for (int mi=0;mi<4;mi++)
#pragma unroll
        for(int ni=0;ni<8;ni++)
#pragma unroll
            for(int q=0;q<4;q++) acc[mi][ni][q]=0.f;

    const int aRow0 = wm*64 + gid;
    const int bCol0 = wn*64 + gid;

    for (int kt=0; kt<KT; kt++){
        asm volatile("cp.async.wait_group %0;\n"::"n"(STAGES-2));
        __syncthreads();
        if (kt + (STAGES-1) < KT) issue(kt+STAGES-1, (kt+STAGES-1)%STAGES);
        cp_commit();

        const uint32_t* uA = (const uint32_t*)(smem + (kt%STAGES)*STAGE_FL);
        const uint32_t* uB = uA + A_FL;
#pragma unroll
        for (int kk=0; kk<TK; kk+=8){
            uint32_t a[4][4], b[8][2];
#pragma unroll
            for (int mi=0;mi<4;mi++){
                int r0 = (aRow0 + mi*16)*A_ST + kk + t4;
                a[mi][0]=uA[r0];
                a[mi][1]=uA[r0+8*A_ST];
                a[mi][2]=uA[r0+4];
                a[mi][3]=uA[r0+8*A_ST+4];
            }
#pragma unroll
            for (int ni=0;ni<8;ni++){
                int c0 = (kk+t4)*B_ST_N + bCol0 + ni*8;
                b[ni][0]=uB[c0]; b[ni][1]=uB[c0+4*B_ST_N];
            }
#pragma unroll
            for (int mi=0;mi<4;mi++)
#pragma unroll
                for (int ni=0;ni<8;ni++)
                    mma_tf32(acc[mi][ni], a[mi][0],a[mi][1],a[mi][2],a[mi][3],
                             b[ni][0],b[ni][1]);
        }
    }
    asm volatile("cp.async.wait_group 0;\n");

    const int epiRow = mBase + wm*64 + gid;
    const int epiCol = nBase + wn*64 + t4*2;
#pragma unroll
    for (int mi=0;mi<4;mi++){
#pragma unroll
        for (int half=0; half<2; half++){
            int r = epiRow + mi*16 + half*8;
            size_t rowOff = (size_t)(r*E_DIM + z)*(size_t)ldC;
#pragma unroll
            for (int ni=0;ni<8;ni++){
                int col = epiCol + ni*8;
                float2 p; p.x = acc[mi][ni][half*2+0]; p.y = acc[mi][ni][half*2+1];
                *(float2*)(C + rowOff + col) = p;
            }
        }
    }
}

// ---------------- GEMM2: legacy s8 IMMA m16n8k32, exp + rowsum epilogue ------
// logit[r][v] = sa[r]*sb[v] * sum_k qa[r][k]*qb[v][k];  Cexp = exp(logit).
// Same 256x128 tile / 8 warps of 64x64 / 3-stage pipeline as the R8 bf16 kernel;
// s8 fragments have identical smem word addressing (20-word padded stride).
#define TK2 64                 // s8 k per tile (64 B rows)
#define A_W (TM*20)            // A tile words (5120)
#define B_W (TN*20)            // B tile words (2560)
#define STAGE_W (A_W + B_W)    // 7680 words
#define SMEM2_BYTES (STAGE_W*STAGES*4)   // 92160 B

__device__ __forceinline__ void mma_s8(int c[4], uint32_t a0,uint32_t a1,uint32_t a2,uint32_t a3,
                                       uint32_t b0,uint32_t b1){
    asm volatile("mma.sync.aligned.m16n8k32.row.col.s32.s8.s8.s32 "
        "{%0,%1,%2,%3},{%4,%5,%6,%7},{%8,%9},{%0,%1,%2,%3};\n"
        : "+r"(c[0]),"+r"(c[1]),"+r"(c[2]),"+r"(c[3])
        : "r"(a0),"r"(a1),"r"(a2),"r"(a3),"r"(b0),"r"(b1));
}

__global__ __launch_bounds__(256)
void gemm2_s8_kernel(const signed char* __restrict__ A,
                     const signed char* __restrict__ B,
                     float* __restrict__ Cexp, int Ntot)
{
    extern __shared__ uint32_t smw[];
    __shared__ float sBt[TN];
    const int tid = threadIdx.x;
    const int mBase = blockIdx.x*TM, nBase = blockIdx.y*TN;
    const uint32_t sbase = (uint32_t)__cvta_generic_to_shared(smw);
    const int KT = H_DIM/TK2;   // 40

    if (tid < TN) sBt[tid] = g_sb[nBase + tid];

    auto issue = [&](int kt, int st){
        uint32_t sA = sbase + (uint32_t)(st*STAGE_W)*4u;
        uint32_t sB = sA + (uint32_t)A_W*4u;
        // A: 256 rows x 64 B -> 1024 chunks of 16B, 4/thread
#pragma unroll
        for (int i=0;i<4;i++){
            int c = tid + i*256;
            int row = c>>2, ch = c&3;                 // ch*16 bytes
            cp16(sA + (uint32_t)(row*80 + ch*16),
                 A + (size_t)(mBase+row)*H_DIM + kt*TK2 + ch*16);
        }
        // B: 128 rows x 64 B -> 512 chunks, 2/thread
#pragma unroll
        for (int i=0;i<2;i++){
            int c = tid + i*256;
            int row = c>>2, ch = c&3;
            cp16(sB + (uint32_t)(row*80 + ch*16),
                 B + (size_t)(nBase+row)*H_DIM + kt*TK2 + ch*16);
        }
    };

    issue(0,0); cp_commit();
    issue(1,1); cp_commit();

    const int warp = tid>>5, lane = tid&31;
    const int wm = warp & 3, wn = warp >> 2;    // 4x2 warps, 64x64 each
    const int gid = lane>>2, t4 = lane&3;

    int acc[4][8][4];
#pragma unroll
    for (int mi=0;mi<4;mi++)
#pragma unroll
        for(int ni=0;ni<8;ni++)
#pragma unroll
            for(int q=0;q<4;q++) acc[mi][ni][q]=0;

    const int aRow0 = wm*64 + gid;
    const int bCol0 = wn*64 + gid;

    for (int kt=0; kt<KT; kt++){
        asm volatile("cp.async.wait_group %0;\n"::"n"(STAGES-2));
        __syncthreads();
        if (kt + (STAGES-1) < KT) issue(kt+STAGES-1, (kt+STAGES-1)%STAGES);
        cp_commit();

        const uint32_t* uA = smw + (kt%STAGES)*STAGE_W;
        const uint32_t* uB = uA + A_W;
#pragma unroll
        for (int k2=0; k2<2; k2++){            // two k32 steps per TK2=64
            const int kw = k2*8 + t4;          // word offset in 20-word row
            uint32_t a[4][4], b[8][2];
#pragma unroll
            for (int mi=0;mi<4;mi++){
                int r0 = (aRow0 + mi*16)*20 + kw;
                // s8 m16n8k32 A-frag: a0=(g,4t4..), a1=(g+8,..), a2=(g,4t4+16..), a3=(g+8,..)
                a[mi][0]=uA[r0];
                a[mi][1]=uA[r0+160];           // +8 rows * 20 words
                a[mi][2]=uA[r0+4];             // +16 bytes = +4 words
                a[mi][3]=uA[r0+164];
            }
#pragma unroll
            for (int ni=0;ni<8;ni++){
                int c0 = (bCol0 + ni*8)*20 + kw;
                b[ni][0]=uB[c0]; b[ni][1]=uB[c0+4];
            }
#pragma unroll
            for (int mi=0;mi<4;mi++)
#pragma unroll
                for (int ni=0;ni<8;ni++)
                    mma_s8(acc[mi][ni], a[mi][0],a[mi][1],a[mi][2],a[mi][3],
                           b[ni][0],b[ni][1]);
        }
    }
    asm volatile("cp.async.wait_group 0;\n");

    // epilogue: dequant + exp + store + fused row-sum
    const int epiRow = mBase + wm*64 + gid;
    const int epiCol = wn*64 + t4*2;     // tile-local column
#pragma unroll
    for (int mi=0;mi<4;mi++){
#pragma unroll
        for (int half=0; half<2; half++){
            int r = epiRow + mi*16 + half*8;
            float sa = g_sa[r];
            size_t rowOff = (size_t)r*(size_t)LDE + nBase;
            float rsum = 0.f;
#pragma unroll
            for (int ni=0;ni<8;ni++){
                int col = epiCol + ni*8;
                float v0 = __expf((float)acc[mi][ni][half*2+0] * sa * sBt[col]);
                float v1 = __expf((float)acc[mi][ni][half*2+1] * sa * sBt[col+1]);
                if (nBase + col + 1 < Ntot){
                    float2 p; p.x=v0; p.y=v1;
                    *(float2*)(Cexp + rowOff + col) = p;
                    rsum += v0 + v1;
                } else if (nBase + col < Ntot){
                    Cexp[rowOff+col] = v0;
                    rsum += v0;
                }
            }
            rsum += __shfl_xor_sync(0xffffffffu, rsum, 1);
            rsum += __shfl_xor_sync(0xffffffffu, rsum, 2);
            if (t4 == 0) atomicAdd(&g_Z[r], rsum);
        }
    }
}

// ---------------- final: mixture + log ---------------------------------------
__global__ void final_kernel(float* __restrict__ out){
    int s = blockIdx.y;
    int v = blockIdx.x*256 + threadIdx.x;
    __shared__ float w[E_DIM];
    if (threadIdx.x < E_DIM){
        int idx = s*E_DIM + threadIdx.x;
        w[threadIdx.x] = g_gate[idx] / g_Z[idx];
    }
    __syncthreads();
    if (v < V_DIM){
        const float* base = g_expl + (size_t)(s*E_DIM)*LDE + v;
        float acc = 0.f;
#pragma unroll
        for (int e=0;e<E_DIM;e++) acc += w[e]*base[(size_t)e*LDE];
        out[(size_t)s*V_DIM + v] = logf(acc + 1e-10f);
    }
}

// ---------------- launch -----------------------------------------------------
extern "C" void kernel_launch(void* const* d_in, const int* in_sizes, int n_in,
                              void* d_out, int out_size){
    const float* hid  = (const float*)d_in[0];
    const float* emb  = (const float*)d_in[1];
    const float* nsc  = (const float*)d_in[2];
    const float* expw = (const float*)d_in[3];
    const float* gw   = (const float*)d_in[4];
    float* out = (float*)d_out;

    cudaFuncSetAttribute(gemm1_tf32_kernel,
                         cudaFuncAttributeMaxDynamicSharedMemorySize, SMEM1_BYTES);
    cudaFuncSetAttribute(gemm2_s8_kernel,
                         cudaFuncAttributeMaxDynamicSharedMemorySize, SMEM2_BYTES);

    float *ph, *peh, *pexpl;
    signed char *pqa, *pqb;
    cudaGetSymbolAddress((void**)&ph,    g_h);
    cudaGetSymbolAddress((void**)&peh,   g_eh);
    cudaGetSymbolAddress((void**)&pqa,   g_qa);
    cudaGetSymbolAddress((void**)&pqb,   g_qb);
    cudaGetSymbolAddress((void**)&pexpl, g_expl);

    // 1) rmsnorm + gate softmax
    prep_kernel<<<S_DIM, 256>>>(hid, nsc, gw);

    // 2) embedding -> s8 per-row quant (padded rows zeroed) ; zero Z
    quantB_kernel<<<VPAD, 256>>>(emb);
    zeroZ_kernel<<<(R_DIM+255)/256, 256>>>();

    // 3) expert_hidden (tf32), fp32 out; row r = s*E + e
    {
        dim3 g(1, H_DIM/TN, E_DIM);
        gemm1_tf32_kernel<<<g, 256, SMEM1_BYTES>>>(
            ph, expw, peh, H_DIM, H_DIM, H_DIM, H_DIM);
    }

    // 4) quantize expert_hidden rows to s8
    quantA_kernel<<<R_DIM, 256>>>();

    // 5) exp(logits) via s8 IMMA + fused rowsum; M fastest for L2 B reuse
    {
        dim3 g(R_DIM/TM, (V_DIM + TN - 1)/TN, 1);   // (10, 393)
        gemm2_s8_kernel<<<g, 256, SMEM2_BYTES>>>(pqa, pqb, pexpl, V_DIM);
    }

    // 6) mixture + log
    {
        dim3 g((V_DIM + 255)/256, S_DIM, 1);
        final_kernel<<<g, 256>>>(out);
    }
}

// round 11
// speedup vs baseline: 1.8222x; 1.8222x over previous
#include <cuda_runtime.h>
#include <cuda_fp16.h>
#include <cstdint>
#include <cstddef>

#define H_DIM 2560
#define S_DIM 256
#define E_DIM 10
#define V_DIM 50257
#define VPAD  50432            // 197*256 (embh row padding)
#define LDE   50304            // padded expl stride = 393*128
#define R_DIM (S_DIM*E_DIM)    // 2560

// ---------------- scratch (static device allocations) -----------------------
__device__ float g_h[S_DIM*H_DIM];
__device__ __half g_ehh[(size_t)R_DIM*H_DIM];              // GEMM1 out, fp16
__device__ __half g_embh[(size_t)VPAD*H_DIM];              // embedding fp16, padded
__device__ float g_expl[(size_t)R_DIM*LDE];                // exp(logits)
__device__ float g_Z[R_DIM];                               // row sums (atomic)
__device__ float g_gate[S_DIM*E_DIM];

__device__ __forceinline__ float tf32_rna(float x){
    uint32_t u; asm("cvt.rna.tf32.f32 %0, %1;" : "=r"(u) : "f"(x));
    return __uint_as_float(u);
}

__device__ __forceinline__ void cp16(uint32_t d, const void* s){
    asm volatile("cp.async.cg.shared.global [%0], [%1], 16;\n" :: "r"(d), "l"(s));
}
__device__ __forceinline__ void cp_commit(){ asm volatile("cp.async.commit_group;\n"); }

// ---------------- kernel 1: rmsnorm + gate softmax ---------------------------
__global__ void prep_kernel(const float* __restrict__ hid,
                            const float* __restrict__ nscale,
                            const float* __restrict__ gateW){
    int s = blockIdx.x, t = threadIdx.x;
    __shared__ float red[256];
    __shared__ float gred[E_DIM][256];
    float x[10];
    float ss = 0.f;
#pragma unroll
    for (int j=0;j<10;j++){ x[j] = hid[s*H_DIM + t + j*256]; ss += x[j]*x[j]; }
    red[t] = ss; __syncthreads();
    for (int off=128; off; off>>=1){ if(t<off) red[t]+=red[t+off]; __syncthreads(); }
    float inv = rsqrtf(red[0]/(float)H_DIM + 1e-5f);
    float ga[E_DIM];
#pragma unroll
    for(int e=0;e<E_DIM;e++) ga[e]=0.f;
#pragma unroll
    for (int j=0;j<10;j++){
        int i = t + j*256;
        float h = x[j]*inv*nscale[i];
        g_h[s*H_DIM + i] = tf32_rna(h);
#pragma unroll
        for(int e=0;e<E_DIM;e++) ga[e] += h*gateW[i*E_DIM + e];
    }
#pragma unroll
    for(int e=0;e<E_DIM;e++) gred[e][t]=ga[e];
    __syncthreads();
    for(int off=128; off; off>>=1){
        if(t<off){
#pragma unroll
            for(int e=0;e<E_DIM;e++) gred[e][t]+=gred[e][t+off];
        }
        __syncthreads();
    }
    if (t==0){
        float m=-1e30f;
#pragma unroll
        for(int e=0;e<E_DIM;e++) m=fmaxf(m,gred[e][0]);
        float sum=0.f; float ex[E_DIM];
#pragma unroll
        for(int e=0;e<E_DIM;e++){ ex[e]=expf(gred[e][0]-m); sum+=ex[e]; }
#pragma unroll
        for(int e=0;e<E_DIM;e++) g_gate[s*E_DIM+e]=ex[e]/sum;
    }
}

// ---------------- embedding fp32 -> fp16 (padded, zero tail) -----------------
__global__ void embconv_kernel(const float* __restrict__ emb){
    int row = blockIdx.x, t = threadIdx.x;
    __half2* dst = (__half2*)(g_embh + (size_t)row*H_DIM);
    if (row < V_DIM){
        const float2* src = (const float2*)(emb + (size_t)row*H_DIM);
        for (int i=t; i<H_DIM/2; i+=256){
            float2 v = src[i];
            dst[i] = __floats2half2_rn(v.x, v.y);
        }
    } else {
        for (int i=t; i<H_DIM/2; i+=256) dst[i] = __floats2half2_rn(0.f, 0.f);
    }
}

__global__ void zeroZ_kernel(){
    int i = blockIdx.x*256 + threadIdx.x;
    if (i < R_DIM) g_Z[i] = 0.f;
}

// ---------------- GEMM1: legacy tf32 mma, fp16 output ------------------------
#define TM 256
#define TN 128
#define TK 32
#define STAGES 3
#define A_ST 36
#define B_ST_N 132
#define A_FL (TM*A_ST)
#define B_FL (TN*36)
#define STAGE_FL (A_FL + B_FL)
#define SMEM1_BYTES (STAGE_FL*STAGES*4)

__device__ __forceinline__ void mma_tf32(float c[4], uint32_t a0,uint32_t a1,uint32_t a2,uint32_t a3,
                                         uint32_t b0,uint32_t b1){
    asm volatile("mma.sync.aligned.m16n8k8.row.col.f32.tf32.tf32.f32 "
        "{%0,%1,%2,%3},{%4,%5,%6,%7},{%8,%9},{%0,%1,%2,%3};\n"
        : "+f"(c[0]),"+f"(c[1]),"+f"(c[2]),"+f"(c[3])
        : "r"(a0),"r"(a1),"r"(a2),"r"(a3),"r"(b0),"r"(b1));
}

__global__ __launch_bounds__(256)
void gemm1_tf32_kernel(const float* __restrict__ A, const float* __restrict__ Bg,
                       __half* __restrict__ C,
                       int K, int ldA, int ldB, int ldC)
{
    extern __shared__ float smem[];
    const int tid = threadIdx.x;
    const int mBase = blockIdx.x*TM, nBase = blockIdx.y*TN;
    const int z = blockIdx.z;
    const float* B = Bg + (size_t)z*(size_t)H_DIM*H_DIM;
    const uint32_t sbase = (uint32_t)__cvta_generic_to_shared(smem);
    const int KT = K/TK;

    auto issue = [&](int kt, int st){
        uint32_t sA = sbase + (uint32_t)(st*STAGE_FL)*4u;
        uint32_t sB = sA + (uint32_t)A_FL*4u;
#pragma unroll
        for (int i=0;i<8;i++){
            int c = tid + i*256;
            int row = c>>3, kc=(c&7)*4;
            cp16(sA + (uint32_t)(row*A_ST+kc)*4u,
                 A + (size_t)(mBase+row)*ldA + kt*TK + kc);
        }
#pragma unroll
        for (int i=0;i<4;i++){
            int c = tid + i*256;
            int k=c>>5, nc=(c&31)*4;
            cp16(sB + (uint32_t)(k*B_ST_N+nc)*4u,
                 B + (size_t)(kt*TK+k)*ldB + nBase + nc);
        }
    };

    issue(0,0); cp_commit();
    issue(1,1); cp_commit();

    const int warp = tid>>5, lane = tid&31;
    const int wm = warp & 3, wn = warp >> 2;
    const int gid = lane>>2, t4 = lane&3;

    float acc[4][8][4];
#pragma unroll
    for (int mi=0;mi<4;mi++)
#pragma unroll
        for(int ni=0;ni<8;ni++)
#pragma unroll
            for(int q=0;q<4;q++) acc[mi][ni][q]=0.f;

    const int aRow0 = wm*64 + gid;
    const int bCol0 = wn*64 + gid;

    for (int kt=0; kt<KT; kt++){
        asm volatile("cp.async.wait_group %0;\n"::"n"(STAGES-2));
        __syncthreads();
        if (kt + (STAGES-1) < KT) issue(kt+STAGES-1, (kt+STAGES-1)%STAGES);
        cp_commit();

        const uint32_t* uA = (const uint32_t*)(smem + (kt%STAGES)*STAGE_FL);
        const uint32_t* uB = uA + A_FL;
#pragma unroll
        for (int kk=0; kk<TK; kk+=8){
            uint32_t a[4][4], b[8][2];
#pragma unroll
            for (int mi=0;mi<4;mi++){
                int r0 = (aRow0 + mi*16)*A_ST + kk + t4;
                a[mi][0]=uA[r0];
                a[mi][1]=uA[r0+8*A_ST];
                a[mi][2]=uA[r0+4];
                a[mi][3]=uA[r0+8*A_ST+4];
            }
#pragma unroll
            for (int ni=0;ni<8;ni++){
                int c0 = (kk+t4)*B_ST_N + bCol0 + ni*8;
                b[ni][0]=uB[c0]; b[ni][1]=uB[c0+4*B_ST_N];
            }
#pragma unroll
            for (int mi=0;mi<4;mi++)
#pragma unroll
                for (int ni=0;ni<8;ni++)
                    mma_tf32(acc[mi][ni], a[mi][0],a[mi][1],a[mi][2],a[mi][3],
                             b[ni][0],b[ni][1]);
        }
    }
    asm volatile("cp.async.wait_group 0;\n");

    const int epiRow = mBase + wm*64 + gid;
    const int epiCol = nBase + wn*64 + t4*2;
#pragma unroll
    for (int mi=0;mi<4;mi++){
#pragma unroll
        for (int half=0; half<2; half++){
            int r = epiRow + mi*16 + half*8;
            size_t rowOff = (size_t)(r*E_DIM + z)*(size_t)ldC;
#pragma unroll
            for (int ni=0;ni<8;ni++){
                int col = epiCol + ni*8;
                __half2 p = __floats2half2_rn(acc[mi][ni][half*2+0],
                                              acc[mi][ni][half*2+1]);
                *(__half2*)(C + rowOff + col) = p;
            }
        }
    }
}

// ---------------- GEMM2: legacy fp16 m16n8k16 with f16 accum -----------------
// Cexp[r][v] = exp( sum_k A[r][k] * B[v][k] ); also g_Z[r] += row partials.
// A = g_ehh [2560,2560] fp16 row-major; B = g_embh [VPAD,2560] fp16 row-major.
// Two-level accumulation: packed-f16 D regs for 8 kt (K=256), spilled to f32.
#define TK2 32                 // fp16 k per tile (64 B rows)
#define A_W (TM*20)            // A tile words (5120)
#define B_W (TN*20)            // B tile words (2560)
#define STAGE_W (A_W + B_W)    // 7680 words
#define SMEM2_BYTES (STAGE_W*STAGES*4)   // 92160 B
#define SPILL_KT 8             // spill every 8 kt (K=256)

__device__ __forceinline__ void mma_f16acc(uint32_t c[2], uint32_t a0,uint32_t a1,uint32_t a2,uint32_t a3,
                                           uint32_t b0,uint32_t b1){
    asm volatile("mma.sync.aligned.m16n8k16.row.col.f16.f16.f16.f16 "
        "{%0,%1},{%2,%3,%4,%5},{%6,%7},{%0,%1};\n"
        : "+r"(c[0]),"+r"(c[1])
        : "r"(a0),"r"(a1),"r"(a2),"r"(a3),"r"(b0),"r"(b1));
}

__global__ __launch_bounds__(256)
void gemm2_f16_kernel(const __half* __restrict__ A,
                      const __half* __restrict__ B,
                      float* __restrict__ Cexp, int Ntot)
{
    extern __shared__ uint32_t smw[];
    const int tid = threadIdx.x;
    const int mBase = blockIdx.x*TM, nBase = blockIdx.y*TN;
    const uint32_t sbase = (uint32_t)__cvta_generic_to_shared(smw);
    const int KT = H_DIM/TK2;   // 80

    auto issue = [&](int kt, int st){
        uint32_t sA = sbase + (uint32_t)(st*STAGE_W)*4u;
        uint32_t sB = sA + (uint32_t)A_W*4u;
        // A: 256 rows x 64 B -> 1024 chunks of 16B, 4/thread
#pragma unroll
        for (int i=0;i<4;i++){
            int c = tid + i*256;
            int row = c>>2, ch = c&3;                 // ch*16 B = ch*8 halves
            cp16(sA + (uint32_t)(row*80 + ch*16),
                 A + (size_t)(mBase+row)*H_DIM + kt*TK2 + ch*8);
        }
        // B: 128 rows x 64 B -> 512 chunks, 2/thread
#pragma unroll
        for (int i=0;i<2;i++){
            int c = tid + i*256;
            int row = c>>2, ch = c&3;
            cp16(sB + (uint32_t)(row*80 + ch*16),
                 B + (size_t)(nBase+row)*H_DIM + kt*TK2 + ch*8);
        }
    };

    issue(0,0); cp_commit();
    issue(1,1); cp_commit();

    const int warp = tid>>5, lane = tid&31;
    const int wm = warp & 3, wn = warp >> 2;    // 4x2 warps, 64x64 each
    const int gid = lane>>2, t4 = lane&3;

    float acc[4][8][4];          // f32 master accumulators
    uint32_t hacc[4][8][2];      // packed-f16 chunk accumulators
#pragma unroll
    for (int mi=0;mi<4;mi++)
#pragma unroll
        for(int ni=0;ni<8;ni++){
#pragma unroll
            for(int q=0;q<4;q++) acc[mi][ni][q]=0.f;
            hacc[mi][ni][0]=0u; hacc[mi][ni][1]=0u;
        }

    const int aRow0 = wm*64 + gid;
    const int bCol0 = wn*64 + gid;

    for (int kt=0; kt<KT; kt++){
        asm volatile("cp.async.wait_group %0;\n"::"n"(STAGES-2));
        __syncthreads();
        if (kt + (STAGES-1) < KT) issue(kt+STAGES-1, (kt+STAGES-1)%STAGES);
        cp_commit();

        const uint32_t* uA = smw + (kt%STAGES)*STAGE_W;
        const uint32_t* uB = uA + A_W;
#pragma unroll
        for (int k2=0; k2<2; k2++){            // two k16 steps per TK2=32
            const int kw = k2*8 + t4;          // word offset in row
            uint32_t a[4][4], b[8][2];
#pragma unroll
            for (int mi=0;mi<4;mi++){
                int r0 = (aRow0 + mi*16)*20 + kw;
                // m16n8k16 f16 A-frag: a0=(g,2t4..), a1=(g+8,..), a2=(g,2t4+8..), a3=(g+8,..)
                a[mi][0]=uA[r0];
                a[mi][1]=uA[r0+160];           // +8 rows * 20 words
                a[mi][2]=uA[r0+4];             // +8 halves = +4 words
                a[mi][3]=uA[r0+164];
            }
#pragma unroll
            for (int ni=0;ni<8;ni++){
                int c0 = (bCol0 + ni*8)*20 + kw;
                b[ni][0]=uB[c0]; b[ni][1]=uB[c0+4];
            }
#pragma unroll
            for (int mi=0;mi<4;mi++)
#pragma unroll
                for (int ni=0;ni<8;ni++)
                    mma_f16acc(hacc[mi][ni], a[mi][0],a[mi][1],a[mi][2],a[mi][3],
                               b[ni][0],b[ni][1]);
        }
        if (((kt+1) & (SPILL_KT-1)) == 0){
            // spill f16 chunk accumulators into f32 masters, rezero
#pragma unroll
            for (int mi=0;mi<4;mi++)
#pragma unroll
                for (int ni=0;ni<8;ni++){
                    float2 f0 = __half22float2(*(__half2*)&hacc[mi][ni][0]);
                    float2 f1 = __half22float2(*(__half2*)&hacc[mi][ni][1]);
                    acc[mi][ni][0]+=f0.x; acc[mi][ni][1]+=f0.y;
                    acc[mi][ni][2]+=f1.x; acc[mi][ni][3]+=f1.y;
                    hacc[mi][ni][0]=0u;   hacc[mi][ni][1]=0u;
                }
        }
    }
    asm volatile("cp.async.wait_group 0;\n");

    // epilogue: exp + store + fused row-sum (shfl over t4 group, 1 atomic per slice)
    const int epiRow = mBase + wm*64 + gid;
    const int epiCol = nBase + wn*64 + t4*2;
#pragma unroll
    for (int mi=0;mi<4;mi++){
#pragma unroll
        for (int half=0; half<2; half++){
            int r = epiRow + mi*16 + half*8;
            size_t rowOff = (size_t)r*(size_t)LDE;
            float rsum = 0.f;
#pragma unroll
            for (int ni=0;ni<8;ni++){
                int col = epiCol + ni*8;
                float v0 = __expf(acc[mi][ni][half*2+0]);
                float v1 = __expf(acc[mi][ni][half*2+1]);
                if (col+1 < Ntot){
                    float2 p; p.x=v0; p.y=v1;
                    *(float2*)(Cexp + rowOff + col) = p;
                    rsum += v0 + v1;
                } else if (col < Ntot){
                    Cexp[rowOff+col] = v0;
                    rsum += v0;
                }
            }
            rsum += __shfl_xor_sync(0xffffffffu, rsum, 1);
            rsum += __shfl_xor_sync(0xffffffffu, rsum, 2);
            if (t4 == 0) atomicAdd(&g_Z[r], rsum);
        }
    }
}

// ---------------- final: mixture + log ---------------------------------------
__global__ void final_kernel(float* __restrict__ out){
    int s = blockIdx.y;
    int v = blockIdx.x*256 + threadIdx.x;
    __shared__ float w[E_DIM];
    if (threadIdx.x < E_DIM){
        int idx = s*E_DIM + threadIdx.x;
        w[threadIdx.x] = g_gate[idx] / g_Z[idx];
    }
    __syncthreads();
    if (v < V_DIM){
        const float* base = g_expl + (size_t)(s*E_DIM)*LDE + v;
        float acc = 0.f;
#pragma unroll
        for (int e=0;e<E_DIM;e++) acc += w[e]*base[(size_t)e*LDE];
        out[(size_t)s*V_DIM + v] = logf(acc + 1e-10f);
    }
}

// ---------------- launch -----------------------------------------------------
extern "C" void kernel_launch(void* const* d_in, const int* in_sizes, int n_in,
                              void* d_out, int out_size){
    const float* hid  = (const float*)d_in[0];
    const float* emb  = (const float*)d_in[1];
    const float* nsc  = (const float*)d_in[2];
    const float* expw = (const float*)d_in[3];
    const float* gw   = (const float*)d_in[4];
    float* out = (float*)d_out;

    cudaFuncSetAttribute(gemm1_tf32_kernel,
                         cudaFuncAttributeMaxDynamicSharedMemorySize, SMEM1_BYTES);
    cudaFuncSetAttribute(gemm2_f16_kernel,
                         cudaFuncAttributeMaxDynamicSharedMemorySize, SMEM2_BYTES);

    float *ph, *pexpl;
    __half *pehh, *pembh;
    cudaGetSymbolAddress((void**)&ph,    g_h);
    cudaGetSymbolAddress((void**)&pehh,  g_ehh);
    cudaGetSymbolAddress((void**)&pembh, g_embh);
    cudaGetSymbolAddress((void**)&pexpl, g_expl);

    // 1) rmsnorm + gate softmax
    prep_kernel<<<S_DIM, 256>>>(hid, nsc, gw);

    // 2) embedding -> fp16 (padded rows zeroed) ; zero Z accumulators
    embconv_kernel<<<VPAD, 256>>>(emb);
    zeroZ_kernel<<<(R_DIM+255)/256, 256>>>();

    // 3) expert_hidden (tf32), fp16 out; row r = s*E + e
    {
        dim3 g(1, H_DIM/TN, E_DIM);
        gemm1_tf32_kernel<<<g, 256, SMEM1_BYTES>>>(
            ph, expw, pehh, H_DIM, H_DIM, H_DIM, H_DIM);
    }

    // 4) exp(logits) fp16 tensor cores (f16 accum, chunked) + fused rowsum
    {
        dim3 g(R_DIM/TM, (V_DIM + TN - 1)/TN, 1);   // (10, 393) — M fastest for L2 B reuse
        gemm2_f16_kernel<<<g, 256, SMEM2_BYTES>>>(pehh, pembh, pexpl, V_DIM);
    }

    // 5) mixture + log
    {
        dim3 g((V_DIM + 255)/256, S_DIM, 1);
        final_kernel<<<g, 256>>>(out);
    }
}

// round 12
// speedup vs baseline: 1.9381x; 1.0636x over previous
#include <cuda_runtime.h>
#include <cuda_fp16.h>
#include <cstdint>
#include <cstddef>

#define H_DIM 2560
#define S_DIM 256
#define E_DIM 10
#define V_DIM 50257
#define VPAD  50432            // 197*256 (embh row padding)
#define LDE   50304            // padded expl stride = 393*128
#define R_DIM (S_DIM*E_DIM)    // 2560

// ---------------- scratch (static device allocations) -----------------------
__device__ float g_h[S_DIM*H_DIM];
__device__ __half g_ehh[(size_t)R_DIM*H_DIM];              // GEMM1 out, fp16
__device__ __half g_embh[(size_t)VPAD*H_DIM];              // embedding fp16, padded
__device__ __half g_expl[(size_t)R_DIM*LDE];               // exp(logits), fp16
__device__ float g_Z[R_DIM];                               // row sums (atomic)
__device__ float g_gate[S_DIM*E_DIM];

__device__ __forceinline__ float tf32_rna(float x){
    uint32_t u; asm("cvt.rna.tf32.f32 %0, %1;" : "=r"(u) : "f"(x));
    return __uint_as_float(u);
}

__device__ __forceinline__ void cp16(uint32_t d, const void* s){
    asm volatile("cp.async.cg.shared.global [%0], [%1], 16;\n" :: "r"(d), "l"(s));
}
__device__ __forceinline__ void cp_commit(){ asm volatile("cp.async.commit_group;\n"); }

// ---------------- kernel 1: rmsnorm + gate softmax ---------------------------
__global__ void prep_kernel(const float* __restrict__ hid,
                            const float* __restrict__ nscale,
                            const float* __restrict__ gateW){
    int s = blockIdx.x, t = threadIdx.x;
    __shared__ float red[256];
    __shared__ float gred[E_DIM][256];
    float x[10];
    float ss = 0.f;
#pragma unroll
    for (int j=0;j<10;j++){ x[j] = hid[s*H_DIM + t + j*256]; ss += x[j]*x[j]; }
    red[t] = ss; __syncthreads();
    for (int off=128; off; off>>=1){ if(t<off) red[t]+=red[t+off]; __syncthreads(); }
    float inv = rsqrtf(red[0]/(float)H_DIM + 1e-5f);
    float ga[E_DIM];
#pragma unroll
    for(int e=0;e<E_DIM;e++) ga[e]=0.f;
#pragma unroll
    for (int j=0;j<10;j++){
        int i = t + j*256;
        float h = x[j]*inv*nscale[i];
        g_h[s*H_DIM + i] = tf32_rna(h);
#pragma unroll
        for(int e=0;e<E_DIM;e++) ga[e] += h*gateW[i*E_DIM + e];
    }
#pragma unroll
    for(int e=0;e<E_DIM;e++) gred[e][t]=ga[e];
    __syncthreads();
    for(int off=128; off; off>>=1){
        if(t<off){
#pragma unroll
            for(int e=0;e<E_DIM;e++) gred[e][t]+=gred[e][t+off];
        }
        __syncthreads();
    }
    if (t==0){
        float m=-1e30f;
#pragma unroll
        for(int e=0;e<E_DIM;e++) m=fmaxf(m,gred[e][0]);
        float sum=0.f; float ex[E_DIM];
#pragma unroll
        for(int e=0;e<E_DIM;e++){ ex[e]=expf(gred[e][0]-m); sum+=ex[e]; }
#pragma unroll
        for(int e=0;e<E_DIM;e++) g_gate[s*E_DIM+e]=ex[e]/sum;
    }
}

// ---------------- embedding fp32 -> fp16 (padded, zero tail) -----------------
__global__ void embconv_kernel(const float* __restrict__ emb){
    int row = blockIdx.x, t = threadIdx.x;
    __half2* dst = (__half2*)(g_embh + (size_t)row*H_DIM);
    if (row < V_DIM){
        const float2* src = (const float2*)(emb + (size_t)row*H_DIM);
        for (int i=t; i<H_DIM/2; i+=256){
            float2 v = src[i];
            dst[i] = __floats2half2_rn(v.x, v.y);
        }
    } else {
        for (int i=t; i<H_DIM/2; i+=256) dst[i] = __floats2half2_rn(0.f, 0.f);
    }
}

__global__ void zeroZ_kernel(){
    int i = blockIdx.x*256 + threadIdx.x;
    if (i < R_DIM) g_Z[i] = 0.f;
}

// ---------------- GEMM1: tf32 mma, TM=128, 2 CTAs/SM, 2-stage ---------------
#define T1M 128
#define T1N 128
#define T1K 32
#define A1_ST 36
#define B1_ST 132
#define A1_FL (T1M*A1_ST)          // 4608
#define B1_FL 4608                 // >= 32*132 = 4224
#define STAGE1_FL (A1_FL + B1_FL)  // 9216
#define SMEM1_BYTES (STAGE1_FL*2*4)  // 73728

__device__ __forceinline__ void mma_tf32(float c[4], uint32_t a0,uint32_t a1,uint32_t a2,uint32_t a3,
                                         uint32_t b0,uint32_t b1){
    asm volatile("mma.sync.aligned.m16n8k8.row.col.f32.tf32.tf32.f32 "
        "{%0,%1,%2,%3},{%4,%5,%6,%7},{%8,%9},{%0,%1,%2,%3};\n"
        : "+f"(c[0]),"+f"(c[1]),"+f"(c[2]),"+f"(c[3])
        : "r"(a0),"r"(a1),"r"(a2),"r"(a3),"r"(b0),"r"(b1));
}

__global__ __launch_bounds__(256, 2)
void gemm1_tf32_kernel(const float* __restrict__ A, const float* __restrict__ Bg,
                       __half* __restrict__ C)
{
    extern __shared__ float smem[];
    const int tid = threadIdx.x;
    const int mBase = blockIdx.x*T1M, nBase = blockIdx.y*T1N;
    const int z = blockIdx.z;
    const float* B = Bg + (size_t)z*(size_t)H_DIM*H_DIM;
    const uint32_t sbase = (uint32_t)__cvta_generic_to_shared(smem);
    const int KT = H_DIM/T1K;   // 80

    auto issue = [&](int kt, int st){
        uint32_t sA = sbase + (uint32_t)(st*STAGE1_FL)*4u;
        uint32_t sB = sA + (uint32_t)A1_FL*4u;
        // A: 128 rows x 8 chunks(16B) = 1024, 4/thread
#pragma unroll
        for (int i=0;i<4;i++){
            int c = tid + i*256;
            int row = c>>3, kc=(c&7)*4;
            cp16(sA + (uint32_t)(row*A1_ST+kc)*4u,
                 A + (size_t)(mBase+row)*H_DIM + kt*T1K + kc);
        }
        // B: 32 k-rows x 32 n-chunks = 1024, 4/thread
#pragma unroll
        for (int i=0;i<4;i++){
            int c = tid + i*256;
            int k=c>>5, nc=(c&31)*4;
            cp16(sB + (uint32_t)(k*B1_ST+nc)*4u,
                 B + (size_t)(kt*T1K+k)*H_DIM + nBase + nc);
        }
    };

    issue(0,0); cp_commit();

    const int warp = tid>>5, lane = tid&31;
    const int wm = warp & 3, wn = warp >> 2;    // 4 m-warps (32 rows) x 2 n-warps (64 cols)
    const int gid = lane>>2, t4 = lane&3;

    float acc[2][8][4];
#pragma unroll
    for (int mi=0;mi<2;mi++)
#pragma unroll
        for(int ni=0;ni<8;ni++)
#pragma unroll
            for(int q=0;q<4;q++) acc[mi][ni][q]=0.f;

    const int aRow0 = wm*32 + gid;
    const int bCol0 = wn*64 + gid;

    for (int kt=0; kt<KT; kt++){
        __syncthreads();                        // stage (kt+1)&1 fully consumed
        if (kt+1 < KT) issue(kt+1, (kt+1)&1);
        cp_commit();
        asm volatile("cp.async.wait_group 1;\n");   // stage kt ready
        __syncthreads();

        const uint32_t* uA = (const uint32_t*)(smem + (kt&1)*STAGE1_FL);
        const uint32_t* uB = uA + A1_FL;
#pragma unroll
        for (int kk=0; kk<T1K; kk+=8){
            uint32_t a[2][4], b[8][2];
#pragma unroll
            for (int mi=0;mi<2;mi++){
                int r0 = (aRow0 + mi*16)*A1_ST + kk + t4;
                a[mi][0]=uA[r0];
                a[mi][1]=uA[r0+8*A1_ST];
                a[mi][2]=uA[r0+4];
                a[mi][3]=uA[r0+8*A1_ST+4];
            }
#pragma unroll
            for (int ni=0;ni<8;ni++){
                int c0 = (kk+t4)*B1_ST + bCol0 + ni*8;
                b[ni][0]=uB[c0]; b[ni][1]=uB[c0+4*B1_ST];
            }
#pragma unroll
            for (int mi=0;mi<2;mi++)
#pragma unroll
                for (int ni=0;ni<8;ni++)
                    mma_tf32(acc[mi][ni], a[mi][0],a[mi][1],a[mi][2],a[mi][3],
                             b[ni][0],b[ni][1]);
        }
    }
    asm volatile("cp.async.wait_group 0;\n");

    const int epiRow = mBase + wm*32 + gid;
    const int epiCol = nBase + wn*64 + t4*2;
#pragma unroll
    for (int mi=0;mi<2;mi++){
#pragma unroll
        for (int half=0; half<2; half++){
            int r = epiRow + mi*16 + half*8;
            size_t rowOff = (size_t)(r*E_DIM + z)*(size_t)H_DIM;
#pragma unroll
            for (int ni=0;ni<8;ni++){
                int col = epiCol + ni*8;
                __half2 p = __floats2half2_rn(acc[mi][ni][half*2+0],
                                              acc[mi][ni][half*2+1]);
                *(__half2*)(C + rowOff + col) = p;
            }
        }
    }
}

// ---------------- GEMM2: fp16 m16n8k16 f32-acc (R8 structure), fp16 out ------
// Cexp[r][v] = exp( sum_k A[r][k] * B[v][k] ); g_Z[r] += row partials.
#define TM 256
#define TN 128
#define TK2 32
#define STAGES 3
#define A_W (TM*20)            // 5120 words
#define B_W (TN*20)            // 2560 words
#define STAGE_W (A_W + B_W)    // 7680 words
#define SMEM2_BYTES (STAGE_W*STAGES*4)   // 92160 B

__device__ __forceinline__ void mma_f16(float c[4], uint32_t a0,uint32_t a1,uint32_t a2,uint32_t a3,
                                        uint32_t b0,uint32_t b1){
    asm volatile("mma.sync.aligned.m16n8k16.row.col.f32.f16.f16.f32 "
        "{%0,%1,%2,%3},{%4,%5,%6,%7},{%8,%9},{%0,%1,%2,%3};\n"
        : "+f"(c[0]),"+f"(c[1]),"+f"(c[2]),"+f"(c[3])
        : "r"(a0),"r"(a1),"r"(a2),"r"(a3),"r"(b0),"r"(b1));
}

__global__ __launch_bounds__(256)
void gemm2_f16_kernel(const __half* __restrict__ A,
                      const __half* __restrict__ B,
                      __half* __restrict__ Cexp, int Ntot)
{
    extern __shared__ uint32_t smw[];
    const int tid = threadIdx.x;
    const int mBase = blockIdx.x*TM, nBase = blockIdx.y*TN;
    const uint32_t sbase = (uint32_t)__cvta_generic_to_shared(smw);
    const int KT = H_DIM/TK2;   // 80

    auto issue = [&](int kt, int st){
        uint32_t sA = sbase + (uint32_t)(st*STAGE_W)*4u;
        uint32_t sB = sA + (uint32_t)A_W*4u;
#pragma unroll
        for (int i=0;i<4;i++){
            int c = tid + i*256;
            int row = c>>2, ch = c&3;
            cp16(sA + (uint32_t)(row*80 + ch*16),
                 A + (size_t)(mBase+row)*H_DIM + kt*TK2 + ch*8);
        }
#pragma unroll
        for (int i=0;i<2;i++){
            int c = tid + i*256;
            int row = c>>2, ch = c&3;
            cp16(sB + (uint32_t)(row*80 + ch*16),
                 B + (size_t)(nBase+row)*H_DIM + kt*TK2 + ch*8);
        }
    };

    issue(0,0); cp_commit();
    issue(1,1); cp_commit();

    const int warp = tid>>5, lane = tid&31;
    const int wm = warp & 3, wn = warp >> 2;    // 4x2 warps, 64x64 each
    const int gid = lane>>2, t4 = lane&3;

    float acc[4][8][4];
#pragma unroll
    for (int mi=0;mi<4;mi++)
#pragma unroll
        for(int ni=0;ni<8;ni++)
#pragma unroll
            for(int q=0;q<4;q++) acc[mi][ni][q]=0.f;

    const int aRow0 = wm*64 + gid;
    const int bCol0 = wn*64 + gid;

    for (int kt=0; kt<KT; kt++){
        asm volatile("cp.async.wait_group %0;\n"::"n"(STAGES-2));
        __syncthreads();
        if (kt + (STAGES-1) < KT) issue(kt+STAGES-1, (kt+STAGES-1)%STAGES);
        cp_commit();

        const uint32_t* uA = smw + (kt%STAGES)*STAGE_W;
        const uint32_t* uB = uA + A_W;
#pragma unroll
        for (int k2=0; k2<2; k2++){
            const int kw = k2*8 + t4;
            uint32_t a[4][4], b[8][2];
#pragma unroll
            for (int mi=0;mi<4;mi++){
                int r0 = (aRow0 + mi*16)*20 + kw;
                a[mi][0]=uA[r0];
                a[mi][1]=uA[r0+160];
                a[mi][2]=uA[r0+4];
                a[mi][3]=uA[r0+164];
            }
#pragma unroll
            for (int ni=0;ni<8;ni++){
                int c0 = (bCol0 + ni*8)*20 + kw;
                b[ni][0]=uB[c0]; b[ni][1]=uB[c0+4];
            }
#pragma unroll
            for (int mi=0;mi<4;mi++)
#pragma unroll
                for (int ni=0;ni<8;ni++)
                    mma_f16(acc[mi][ni], a[mi][0],a[mi][1],a[mi][2],a[mi][3],
                            b[ni][0],b[ni][1]);
        }
    }
    asm volatile("cp.async.wait_group 0;\n");

    // epilogue: exp + fp16 store + fused row-sum
    const int epiRow = mBase + wm*64 + gid;
    const int epiCol = nBase + wn*64 + t4*2;
#pragma unroll
    for (int mi=0;mi<4;mi++){
#pragma unroll
        for (int half=0; half<2; half++){
            int r = epiRow + mi*16 + half*8;
            size_t rowOff = (size_t)r*(size_t)LDE;
            float rsum = 0.f;
#pragma unroll
            for (int ni=0;ni<8;ni++){
                int col = epiCol + ni*8;
                float v0 = __expf(acc[mi][ni][half*2+0]);
                float v1 = __expf(acc[mi][ni][half*2+1]);
                if (col+1 < Ntot){
                    *(__half2*)(Cexp + rowOff + col) = __floats2half2_rn(v0, v1);
                    rsum += v0 + v1;
                } else if (col < Ntot){
                    Cexp[rowOff+col] = __float2half_rn(v0);
                    rsum += v0;
                }
            }
            rsum += __shfl_xor_sync(0xffffffffu, rsum, 1);
            rsum += __shfl_xor_sync(0xffffffffu, rsum, 2);
            if (t4 == 0) atomicAdd(&g_Z[r], rsum);
        }
    }
}

// ---------------- final: mixture + log (fp16 reads) --------------------------
__global__ void final_kernel(float* __restrict__ out){
    int s = blockIdx.y;
    int v = blockIdx.x*256 + threadIdx.x;
    __shared__ float w[E_DIM];
    if (threadIdx.x < E_DIM){
        int idx = s*E_DIM + threadIdx.x;
        w[threadIdx.x] = g_gate[idx] / g_Z[idx];
    }
    __syncthreads();
    if (v < V_DIM){
        const __half* base = g_expl + (size_t)(s*E_DIM)*LDE + v;
        float acc = 0.f;
#pragma unroll
        for (int e=0;e<E_DIM;e++) acc += w[e]*__half2float(base[(size_t)e*LDE]);
        out[(size_t)s*V_DIM + v] = logf(acc + 1e-10f);
    }
}

// ---------------- launch -----------------------------------------------------
extern "C" void kernel_launch(void* const* d_in, const int* in_sizes, int n_in,
                              void* d_out, int out_size){
    const float* hid  = (const float*)d_in[0];
    const float* emb  = (const float*)d_in[1];
    const float* nsc  = (const float*)d_in[2];
    const float* expw = (const float*)d_in[3];
    const float* gw   = (const float*)d_in[4];
    float* out = (float*)d_out;

    cudaFuncSetAttribute(gemm1_tf32_kernel,
                         cudaFuncAttributeMaxDynamicSharedMemorySize, SMEM1_BYTES);
    cudaFuncSetAttribute(gemm2_f16_kernel,
                         cudaFuncAttributeMaxDynamicSharedMemorySize, SMEM2_BYTES);

    float *ph;
    __half *pehh, *pembh, *pexpl;
    cudaGetSymbolAddress((void**)&ph,    g_h);
    cudaGetSymbolAddress((void**)&pehh,  g_ehh);
    cudaGetSymbolAddress((void**)&pembh, g_embh);
    cudaGetSymbolAddress((void**)&pexpl, g_expl);

    // 1) rmsnorm + gate softmax
    prep_kernel<<<S_DIM, 256>>>(hid, nsc, gw);

    // 2) embedding -> fp16 (padded rows zeroed) ; zero Z accumulators
    embconv_kernel<<<VPAD, 256>>>(emb);
    zeroZ_kernel<<<(R_DIM+255)/256, 256>>>();

    // 3) expert_hidden (tf32, 2 CTA/SM), fp16 out; row r = s*E + e
    {
        dim3 g(S_DIM/T1M, H_DIM/T1N, E_DIM);   // (2, 20, 10) = 400 CTAs
        gemm1_tf32_kernel<<<g, 256, SMEM1_BYTES>>>(ph, expw, pehh);
    }

    // 4) exp(logits) fp16 tensor cores (f32 acc) + fused rowsum, fp16 out
    {
        dim3 g(R_DIM/TM, (V_DIM + TN - 1)/TN, 1);   // (10, 393) — M fastest for L2 B reuse
        gemm2_f16_kernel<<<g, 256, SMEM2_BYTES>>>(pehh, pembh, pexpl, V_DIM);
    }

    // 5) mixture + log
    {
        dim3 g((V_DIM + 255)/256, S_DIM, 1);
        final_kernel<<<g, 256>>>(out);
    }
}

// round 13
// speedup vs baseline: 2.2418x; 1.1567x over previous
#include <cuda_runtime.h>
#include <cuda_fp16.h>
#include <cstdint>
#include <cstddef>

#define H_DIM 2560
#define S_DIM 256
#define E_DIM 10
#define V_DIM 50257
#define VPAD  50432            // 197*256 (embh row padding)
#define LDE   50304            // padded expl stride = 393*128
#define R_DIM (S_DIM*E_DIM)    // 2560

// ---------------- scratch (static device allocations) -----------------------
__device__ float g_h[S_DIM*H_DIM];
__device__ __half g_ehh[(size_t)R_DIM*H_DIM];              // GEMM1 out, fp16
__device__ __half g_embh[(size_t)VPAD*H_DIM];              // embedding fp16, padded
__device__ __half g_expl[(size_t)R_DIM*LDE];               // exp(logits), fp16
__device__ float g_Z[R_DIM];                               // row sums (atomic)
__device__ float g_gate[S_DIM*E_DIM];

__device__ __forceinline__ float tf32_rna(float x){
    uint32_t u; asm("cvt.rna.tf32.f32 %0, %1;" : "=r"(u) : "f"(x));
    return __uint_as_float(u);
}

__device__ __forceinline__ void cp16(uint32_t d, const void* s){
    asm volatile("cp.async.cg.shared.global [%0], [%1], 16;\n" :: "r"(d), "l"(s));
}
__device__ __forceinline__ void cp_commit(){ asm volatile("cp.async.commit_group;\n"); }

// ---------------- kernel 1: rmsnorm + gate softmax ---------------------------
__global__ void prep_kernel(const float* __restrict__ hid,
                            const float* __restrict__ nscale,
                            const float* __restrict__ gateW){
    int s = blockIdx.x, t = threadIdx.x;
    __shared__ float red[256];
    __shared__ float gred[E_DIM][256];
    float x[10];
    float ss = 0.f;
#pragma unroll
    for (int j=0;j<10;j++){ x[j] = hid[s*H_DIM + t + j*256]; ss += x[j]*x[j]; }
    red[t] = ss; __syncthreads();
    for (int off=128; off; off>>=1){ if(t<off) red[t]+=red[t+off]; __syncthreads(); }
    float inv = rsqrtf(red[0]/(float)H_DIM + 1e-5f);
    float ga[E_DIM];
#pragma unroll
    for(int e=0;e<E_DIM;e++) ga[e]=0.f;
#pragma unroll
    for (int j=0;j<10;j++){
        int i = t + j*256;
        float h = x[j]*inv*nscale[i];
        g_h[s*H_DIM + i] = tf32_rna(h);
#pragma unroll
        for(int e=0;e<E_DIM;e++) ga[e] += h*gateW[i*E_DIM + e];
    }
#pragma unroll
    for(int e=0;e<E_DIM;e++) gred[e][t]=ga[e];
    __syncthreads();
    for(int off=128; off; off>>=1){
        if(t<off){
#pragma unroll
            for(int e=0;e<E_DIM;e++) gred[e][t]+=gred[e][t+off];
        }
        __syncthreads();
    }
    if (t==0){
        float m=-1e30f;
#pragma unroll
        for(int e=0;e<E_DIM;e++) m=fmaxf(m,gred[e][0]);
        float sum=0.f; float ex[E_DIM];
#pragma unroll
        for(int e=0;e<E_DIM;e++){ ex[e]=expf(gred[e][0]-m); sum+=ex[e]; }
#pragma unroll
        for(int e=0;e<E_DIM;e++) g_gate[s*E_DIM+e]=ex[e]/sum;
    }
}

// ---------------- embedding fp32 -> fp16 (padded, zero tail) -----------------
__global__ void embconv_kernel(const float* __restrict__ emb){
    int row = blockIdx.x, t = threadIdx.x;
    __half2* dst = (__half2*)(g_embh + (size_t)row*H_DIM);
    if (row < V_DIM){
        const float2* src = (const float2*)(emb + (size_t)row*H_DIM);
        for (int i=t; i<H_DIM/2; i+=256){
            float2 v = src[i];
            dst[i] = __floats2half2_rn(v.x, v.y);
        }
    } else {
        for (int i=t; i<H_DIM/2; i+=256) dst[i] = __floats2half2_rn(0.f, 0.f);
    }
}

__global__ void zeroZ_kernel(){
    int i = blockIdx.x*256 + threadIdx.x;
    if (i < R_DIM) g_Z[i] = 0.f;
}

// ---------------- GEMM1: tf32 mma, TM=128, 2 CTAs/SM, 3-stage ---------------
#define T1M 128
#define T1N 128
#define T1K 32
#define STG1 3
#define A1_ST 36
#define B1_ST 132
#define A1_FL (T1M*A1_ST)          // 4608
#define B1_FL 4608                 // >= 32*132 = 4224
#define STAGE1_FL (A1_FL + B1_FL)  // 9216
#define SMEM1_BYTES (STAGE1_FL*STG1*4)  // 110592 (2 CTAs = 221 KB <= 228 KB)

__device__ __forceinline__ void mma_tf32(float c[4], uint32_t a0,uint32_t a1,uint32_t a2,uint32_t a3,
                                         uint32_t b0,uint32_t b1){
    asm volatile("mma.sync.aligned.m16n8k8.row.col.f32.tf32.tf32.f32 "
        "{%0,%1,%2,%3},{%4,%5,%6,%7},{%8,%9},{%0,%1,%2,%3};\n"
        : "+f"(c[0]),"+f"(c[1]),"+f"(c[2]),"+f"(c[3])
        : "r"(a0),"r"(a1),"r"(a2),"r"(a3),"r"(b0),"r"(b1));
}

__global__ __launch_bounds__(256, 2)
void gemm1_tf32_kernel(const float* __restrict__ A, const float* __restrict__ Bg,
                       __half* __restrict__ C)
{
    extern __shared__ float smem[];
    const int tid = threadIdx.x;
    const int mBase = blockIdx.x*T1M, nBase = blockIdx.y*T1N;
    const int z = blockIdx.z;
    const float* B = Bg + (size_t)z*(size_t)H_DIM*H_DIM;
    const uint32_t sbase = (uint32_t)__cvta_generic_to_shared(smem);
    const int KT = H_DIM/T1K;   // 80

    auto issue = [&](int kt, int st){
        uint32_t sA = sbase + (uint32_t)(st*STAGE1_FL)*4u;
        uint32_t sB = sA + (uint32_t)A1_FL*4u;
        // A: 128 rows x 8 chunks(16B) = 1024, 4/thread
#pragma unroll
        for (int i=0;i<4;i++){
            int c = tid + i*256;
            int row = c>>3, kc=(c&7)*4;
            cp16(sA + (uint32_t)(row*A1_ST+kc)*4u,
                 A + (size_t)(mBase+row)*H_DIM + kt*T1K + kc);
        }
        // B: 32 k-rows x 32 n-chunks = 1024, 4/thread
#pragma unroll
        for (int i=0;i<4;i++){
            int c = tid + i*256;
            int k=c>>5, nc=(c&31)*4;
            cp16(sB + (uint32_t)(k*B1_ST+nc)*4u,
                 B + (size_t)(kt*T1K+k)*H_DIM + nBase + nc);
        }
    };

    issue(0,0); cp_commit();
    issue(1,1); cp_commit();

    const int warp = tid>>5, lane = tid&31;
    const int wm = warp & 3, wn = warp >> 2;    // 4 m-warps (32 rows) x 2 n-warps (64 cols)
    const int gid = lane>>2, t4 = lane&3;

    float acc[2][8][4];
#pragma unroll
    for (int mi=0;mi<2;mi++)
#pragma unroll
        for(int ni=0;ni<8;ni++)
#pragma unroll
            for(int q=0;q<4;q++) acc[mi][ni][q]=0.f;

    const int aRow0 = wm*32 + gid;
    const int bCol0 = wn*64 + gid;

    for (int kt=0; kt<KT; kt++){
        asm volatile("cp.async.wait_group %0;\n"::"n"(STG1-2));
        __syncthreads();
        if (kt + (STG1-1) < KT) issue(kt+STG1-1, (kt+STG1-1)%STG1);
        cp_commit();

        const uint32_t* uA = (const uint32_t*)(smem + (kt%STG1)*STAGE1_FL);
        const uint32_t* uB = uA + A1_FL;
#pragma unroll
        for (int kk=0; kk<T1K; kk+=8){
            uint32_t a[2][4], b[8][2];
#pragma unroll
            for (int mi=0;mi<2;mi++){
                int r0 = (aRow0 + mi*16)*A1_ST + kk + t4;
                a[mi][0]=uA[r0];
                a[mi][1]=uA[r0+8*A1_ST];
                a[mi][2]=uA[r0+4];
                a[mi][3]=uA[r0+8*A1_ST+4];
            }
#pragma unroll
            for (int ni=0;ni<8;ni++){
                int c0 = (kk+t4)*B1_ST + bCol0 + ni*8;
                b[ni][0]=uB[c0]; b[ni][1]=uB[c0+4*B1_ST];
            }
#pragma unroll
            for (int mi=0;mi<2;mi++)
#pragma unroll
                for (int ni=0;ni<8;ni++)
                    mma_tf32(acc[mi][ni], a[mi][0],a[mi][1],a[mi][2],a[mi][3],
                             b[ni][0],b[ni][1]);
        }
    }
    asm volatile("cp.async.wait_group 0;\n");

    const int epiRow = mBase + wm*32 + gid;
    const int epiCol = nBase + wn*64 + t4*2;
#pragma unroll
    for (int mi=0;mi<2;mi++){
#pragma unroll
        for (int half=0; half<2; half++){
            int r = epiRow + mi*16 + half*8;
            size_t rowOff = (size_t)(r*E_DIM + z)*(size_t)H_DIM;
#pragma unroll
            for (int ni=0;ni<8;ni++){
                int col = epiCol + ni*8;
                __half2 p = __floats2half2_rn(acc[mi][ni][half*2+0],
                                              acc[mi][ni][half*2+1]);
                *(__half2*)(C + rowOff + col) = p;
            }
        }
    }
}

// ---------------- GEMM2: fp16 m16n8k16 f32-acc, TK=64, fp16 out --------------
// Cexp[r][v] = exp( sum_k A[r][k] * B[v][k] ); g_Z[r] += row partials.
// Rows: 128 B data + 16 B pad = 144 B = 36 words (36 = 4 mod 32 -> conflict-free,
// same lane-address proof as the 20-word layout).
#define TM 256
#define TN 128
#define TK2 64
#define STAGES 3
#define A2_ST 36               // words per smem row
#define A_W (TM*A2_ST)         // 9216 words
#define B_W (TN*A2_ST)         // 4608 words
#define STAGE_W (A_W + B_W)    // 13824 words
#define SMEM2_BYTES (STAGE_W*STAGES*4)   // 165888 B

__device__ __forceinline__ void mma_f16(float c[4], uint32_t a0,uint32_t a1,uint32_t a2,uint32_t a3,
                                        uint32_t b0,uint32_t b1){
    asm volatile("mma.sync.aligned.m16n8k16.row.col.f32.f16.f16.f32 "
        "{%0,%1,%2,%3},{%4,%5,%6,%7},{%8,%9},{%0,%1,%2,%3};\n"
        : "+f"(c[0]),"+f"(c[1]),"+f"(c[2]),"+f"(c[3])
        : "r"(a0),"r"(a1),"r"(a2),"r"(a3),"r"(b0),"r"(b1));
}

__global__ __launch_bounds__(256)
void gemm2_f16_kernel(const __half* __restrict__ A,
                      const __half* __restrict__ B,
                      __half* __restrict__ Cexp, int Ntot)
{
    extern __shared__ uint32_t smw[];
    const int tid = threadIdx.x;
    const int mBase = blockIdx.x*TM, nBase = blockIdx.y*TN;
    const uint32_t sbase = (uint32_t)__cvta_generic_to_shared(smw);
    const int KT = H_DIM/TK2;   // 40

    auto issue = [&](int kt, int st){
        uint32_t sA = sbase + (uint32_t)(st*STAGE_W)*4u;
        uint32_t sB = sA + (uint32_t)A_W*4u;
        // A: 256 rows x 128 B -> 2048 chunks of 16B, 8/thread
#pragma unroll
        for (int i=0;i<8;i++){
            int c = tid + i*256;
            int row = c>>3, ch = c&7;                 // ch*16 B = ch*8 halves
            cp16(sA + (uint32_t)(row*144 + ch*16),
                 A + (size_t)(mBase+row)*H_DIM + kt*TK2 + ch*8);
        }
        // B: 128 rows x 128 B -> 1024 chunks, 4/thread
#pragma unroll
        for (int i=0;i<4;i++){
            int c = tid + i*256;
            int row = c>>3, ch = c&7;
            cp16(sB + (uint32_t)(row*144 + ch*16),
                 B + (size_t)(nBase+row)*H_DIM + kt*TK2 + ch*8);
        }
    };

    issue(0,0); cp_commit();
    issue(1,1); cp_commit();

    const int warp = tid>>5, lane = tid&31;
    const int wm = warp & 3, wn = warp >> 2;    // 4x2 warps, 64x64 each
    const int gid = lane>>2, t4 = lane&3;

    float acc[4][8][4];
#pragma unroll
    for (int mi=0;mi<4;mi++)
#pragma unroll
        for(int ni=0;ni<8;ni++)
#pragma unroll
            for(int q=0;q<4;q++) acc[mi][ni][q]=0.f;

    const int aRow0 = wm*64 + gid;
    const int bCol0 = wn*64 + gid;

    for (int kt=0; kt<KT; kt++){
        asm volatile("cp.async.wait_group %0;\n"::"n"(STAGES-2));
        __syncthreads();
        if (kt + (STAGES-1) < KT) issue(kt+STAGES-1, (kt+STAGES-1)%STAGES);
        cp_commit();

        const uint32_t* uA = smw + (kt%STAGES)*STAGE_W;
        const uint32_t* uB = uA + A_W;
#pragma unroll
        for (int k4=0; k4<4; k4++){            // four k16 steps per TK2=64
            const int kw = k4*8 + t4;          // word offset in 36-word row
            uint32_t a[4][4], b[8][2];
#pragma unroll
            for (int mi=0;mi<4;mi++){
                int r0 = (aRow0 + mi*16)*A2_ST + kw;
                // m16n8k16 f16 A-frag: a0=(g,2t4..), a1=(g+8,..), a2=(g,2t4+8..), a3=(g+8,..)
                a[mi][0]=uA[r0];
                a[mi][1]=uA[r0+8*A2_ST];       // +8 rows
                a[mi][2]=uA[r0+4];             // +8 halves = +4 words
                a[mi][3]=uA[r0+8*A2_ST+4];
            }
#pragma unroll
            for (int ni=0;ni<8;ni++){
                int c0 = (bCol0 + ni*8)*A2_ST + kw;
                b[ni][0]=uB[c0]; b[ni][1]=uB[c0+4];
            }
#pragma unroll
            for (int mi=0;mi<4;mi++)
#pragma unroll
                for (int ni=0;ni<8;ni++)
                    mma_f16(acc[mi][ni], a[mi][0],a[mi][1],a[mi][2],a[mi][3],
                            b[ni][0],b[ni][1]);
        }
    }
    asm volatile("cp.async.wait_group 0;\n");

    // epilogue: exp + fp16 store + fused row-sum
    const int epiRow = mBase + wm*64 + gid;
    const int epiCol = nBase + wn*64 + t4*2;
#pragma unroll
    for (int mi=0;mi<4;mi++){
#pragma unroll
        for (int half=0; half<2; half++){
            int r = epiRow + mi*16 + half*8;
            size_t rowOff = (size_t)r*(size_t)LDE;
            float rsum = 0.f;
#pragma unroll
            for (int ni=0;ni<8;ni++){
                int col = epiCol + ni*8;
                float v0 = __expf(acc[mi][ni][half*2+0]);
                float v1 = __expf(acc[mi][ni][half*2+1]);
                if (col+1 < Ntot){
                    *(__half2*)(Cexp + rowOff + col) = __floats2half2_rn(v0, v1);
                    rsum += v0 + v1;
                } else if (col < Ntot){
                    Cexp[rowOff+col] = __float2half_rn(v0);
                    rsum += v0;
                }
            }
            rsum += __shfl_xor_sync(0xffffffffu, rsum, 1);
            rsum += __shfl_xor_sync(0xffffffffu, rsum, 2);
            if (t4 == 0) atomicAdd(&g_Z[r], rsum);
        }
    }
}

// ---------------- final: mixture + log (half2 reads) -------------------------
__global__ void final_kernel(float* __restrict__ out){
    int s = blockIdx.y;
    int v2 = blockIdx.x*256 + threadIdx.x;       // half2 index
    __shared__ float w[E_DIM];
    if (threadIdx.x < E_DIM){
        int idx = s*E_DIM + threadIdx.x;
        w[threadIdx.x] = g_gate[idx] / g_Z[idx];
    }
    __syncthreads();
    const int NV2 = V_DIM/2;                     // 25128 full pairs
    if (v2 < NV2){
        const __half* base = g_expl + (size_t)(s*E_DIM)*LDE + 2*v2;
        float a0 = 0.f, a1 = 0.f;
#pragma unroll
        for (int e=0;e<E_DIM;e++){
            float2 p = __half22float2(*(const __half2*)(base + (size_t)e*LDE));
            a0 += w[e]*p.x; a1 += w[e]*p.y;
        }
        size_t o = (size_t)s*V_DIM + 2*v2;
        out[o]   = logf(a0 + 1e-10f);
        out[o+1] = logf(a1 + 1e-10f);
    } else if (v2 == NV2){                       // tail element v = V_DIM-1
        const __half* base = g_expl + (size_t)(s*E_DIM)*LDE + (V_DIM-1);
        float a0 = 0.f;
#pragma unroll
        for (int e=0;e<E_DIM;e++) a0 += w[e]*__half2float(base[(size_t)e*LDE]);
        out[(size_t)s*V_DIM + (V_DIM-1)] = logf(a0 + 1e-10f);
    }
}

// ---------------- launch -----------------------------------------------------
extern "C" void kernel_launch(void* const* d_in, const int* in_sizes, int n_in,
                              void* d_out, int out_size){
    const float* hid  = (const float*)d_in[0];
    const float* emb  = (const float*)d_in[1];
    const float* nsc  = (const float*)d_in[2];
    const float* expw = (const float*)d_in[3];
    const float* gw   = (const float*)d_in[4];
    float* out = (float*)d_out;

    cudaFuncSetAttribute(gemm1_tf32_kernel,
                         cudaFuncAttributeMaxDynamicSharedMemorySize, SMEM1_BYTES);
    cudaFuncSetAttribute(gemm2_f16_kernel,
                         cudaFuncAttributeMaxDynamicSharedMemorySize, SMEM2_BYTES);

    float *ph;
    __half *pehh, *pembh, *pexpl;
    cudaGetSymbolAddress((void**)&ph,    g_h);
    cudaGetSymbolAddress((void**)&pehh,  g_ehh);
    cudaGetSymbolAddress((void**)&pembh, g_embh);
    cudaGetSymbolAddress((void**)&pexpl, g_expl);

    // 1) rmsnorm + gate softmax
    prep_kernel<<<S_DIM, 256>>>(hid, nsc, gw);

    // 2) embedding -> fp16 (padded rows zeroed) ; zero Z accumulators
    embconv_kernel<<<VPAD, 256>>>(emb);
    zeroZ_kernel<<<(R_DIM+255)/256, 256>>>();

    // 3) expert_hidden (tf32, 2 CTA/SM, 3-stage), fp16 out; row r = s*E + e
    {
        dim3 g(S_DIM/T1M, H_DIM/T1N, E_DIM);   // (2, 20, 10) = 400 CTAs
        gemm1_tf32_kernel<<<g, 256, SMEM1_BYTES>>>(ph, expw, pehh);
    }

    // 4) exp(logits) fp16 tensor cores (f32 acc, TK=64) + fused rowsum, fp16 out
    {
        dim3 g(R_DIM/TM, (V_DIM + TN - 1)/TN, 1);   // (10, 393) — M fastest for L2 B reuse
        gemm2_f16_kernel<<<g, 256, SMEM2_BYTES>>>(pehh, pembh, pexpl, V_DIM);
    }

    // 5) mixture + log
    {
        dim3 g((V_DIM/2 + 256)/256, S_DIM, 1);
        final_kernel<<<g, 256>>>(out);
    }
}

// round 15
// speedup vs baseline: 2.3142x; 1.0323x over previous
#include <cuda_runtime.h>
#include <cuda_fp16.h>
#include <cstdint>
#include <cstddef>

#define H_DIM 2560
#define S_DIM 256
#define E_DIM 10
#define V_DIM 50257
#define VPAD  50432            // 197*256 (embh row padding)
#define LDE   50304            // padded expl stride = 393*128
#define R_DIM (S_DIM*E_DIM)    // 2560

// ---------------- scratch (static device allocations) -----------------------
__device__ float g_h[S_DIM*H_DIM];
__device__ __half g_ehh[(size_t)R_DIM*H_DIM];              // GEMM1 out, fp16
__device__ __half g_embh[(size_t)VPAD*H_DIM];              // embedding fp16, padded
__device__ __half g_expl[(size_t)R_DIM*LDE];               // exp(logits), fp16
__device__ float g_Z[R_DIM];                               // row sums (atomic)
__device__ float g_gate[S_DIM*E_DIM];

__device__ __forceinline__ float tf32_rna(float x){
    uint32_t u; asm("cvt.rna.tf32.f32 %0, %1;" : "=r"(u) : "f"(x));
    return __uint_as_float(u);
}

__device__ __forceinline__ void cp16(uint32_t d, const void* s){
    asm volatile("cp.async.cg.shared.global [%0], [%1], 16;\n" :: "r"(d), "l"(s));
}
__device__ __forceinline__ void cp_commit(){ asm volatile("cp.async.commit_group;\n"); }

#define LDSM4(r0,r1,r2,r3,addr) \
    asm volatile("ldmatrix.sync.aligned.m8n8.x4.shared.b16 {%0,%1,%2,%3}, [%4];" \
        : "=r"(r0),"=r"(r1),"=r"(r2),"=r"(r3) : "r"(addr))

// ---------------- kernel 1: rmsnorm + gate softmax ---------------------------
__global__ void prep_kernel(const float* __restrict__ hid,
                            const float* __restrict__ nscale,
                            const float* __restrict__ gateW){
    int s = blockIdx.x, t = threadIdx.x;
    __shared__ float red[256];
    __shared__ float gred[E_DIM][256];
    float x[10];
    float ss = 0.f;
#pragma unroll
    for (int j=0;j<10;j++){ x[j] = hid[s*H_DIM + t + j*256]; ss += x[j]*x[j]; }
    red[t] = ss; __syncthreads();
    for (int off=128; off; off>>=1){ if(t<off) red[t]+=red[t+off]; __syncthreads(); }
    float inv = rsqrtf(red[0]/(float)H_DIM + 1e-5f);
    float ga[E_DIM];
#pragma unroll
    for(int e=0;e<E_DIM;e++) ga[e]=0.f;
#pragma unroll
    for (int j=0;j<10;j++){
        int i = t + j*256;
        float h = x[j]*inv*nscale[i];
        g_h[s*H_DIM + i] = tf32_rna(h);
#pragma unroll
        for(int e=0;e<E_DIM;e++) ga[e] += h*gateW[i*E_DIM + e];
    }
#pragma unroll
    for(int e=0;e<E_DIM;e++) gred[e][t]=ga[e];
    __syncthreads();
    for(int off=128; off; off>>=1){
        if(t<off){
#pragma unroll
            for(int e=0;e<E_DIM;e++) gred[e][t]+=gred[e][t+off];
        }
        __syncthreads();
    }
    if (t==0){
        float m=-1e30f;
#pragma unroll
        for(int e=0;e<E_DIM;e++) m=fmaxf(m,gred[e][0]);
        float sum=0.f; float ex[E_DIM];
#pragma unroll
        for(int e=0;e<E_DIM;e++){ ex[e]=expf(gred[e][0]-m); sum+=ex[e]; }
#pragma unroll
        for(int e=0;e<E_DIM;e++) g_gate[s*E_DIM+e]=ex[e]/sum;
    }
}

// ---------------- embedding fp32 -> fp16 (padded, zero tail) -----------------
__global__ void embconv_kernel(const float* __restrict__ emb){
    int row = blockIdx.x, t = threadIdx.x;
    __half2* dst = (__half2*)(g_embh + (size_t)row*H_DIM);
    if (row < V_DIM){
        const float2* src = (const float2*)(emb + (size_t)row*H_DIM);
        for (int i=t; i<H_DIM/2; i+=256){
            float2 v = src[i];
            dst[i] = __floats2half2_rn(v.x, v.y);
        }
    } else {
        for (int i=t; i<H_DIM/2; i+=256) dst[i] = __floats2half2_rn(0.f, 0.f);
    }
}

__global__ void zeroZ_kernel(){
    int i = blockIdx.x*256 + threadIdx.x;
    if (i < R_DIM) g_Z[i] = 0.f;
}

// ---------------- GEMM1: tf32 mma, TM=128, 2 CTAs/SM, 3-stage ---------------
#define T1M 128
#define T1N 128
#define T1K 32
#define STG1 3
#define A1_ST 36
#define B1_ST 132
#define A1_FL (T1M*A1_ST)          // 4608
#define B1_FL 4608                 // >= 32*132 = 4224
#define STAGE1_FL (A1_FL + B1_FL)  // 9216
#define SMEM1_BYTES (STAGE1_FL*STG1*4)  // 110592 (2 CTAs = 221 KB <= 228 KB)

__device__ __forceinline__ void mma_tf32(float c[4], uint32_t a0,uint32_t a1,uint32_t a2,uint32_t a3,
                                         uint32_t b0,uint32_t b1){
    asm volatile("mma.sync.aligned.m16n8k8.row.col.f32.tf32.tf32.f32 "
        "{%0,%1,%2,%3},{%4,%5,%6,%7},{%8,%9},{%0,%1,%2,%3};\n"
        : "+f"(c[0]),"+f"(c[1]),"+f"(c[2]),"+f"(c[3])
        : "r"(a0),"r"(a1),"r"(a2),"r"(a3),"r"(b0),"r"(b1));
}

__global__ __launch_bounds__(256, 2)
void gemm1_tf32_kernel(const float* __restrict__ A, const float* __restrict__ Bg,
                       __half* __restrict__ C)
{
    extern __shared__ float smem[];
    const int tid = threadIdx.x;
    const int mBase = blockIdx.x*T1M, nBase = blockIdx.y*T1N;
    const int z = blockIdx.z;
    const float* B = Bg + (size_t)z*(size_t)H_DIM*H_DIM;
    const uint32_t sbase = (uint32_t)__cvta_generic_to_shared(smem);
    const int KT = H_DIM/T1K;   // 80

    auto issue = [&](int kt, int st){
        uint32_t sA = sbase + (uint32_t)(st*STAGE1_FL)*4u;
        uint32_t sB = sA + (uint32_t)A1_FL*4u;
#pragma unroll
        for (int i=0;i<4;i++){
            int c = tid + i*256;
            int row = c>>3, kc=(c&7)*4;
            cp16(sA + (uint32_t)(row*A1_ST+kc)*4u,
                 A + (size_t)(mBase+row)*H_DIM + kt*T1K + kc);
        }
#pragma unroll
        for (int i=0;i<4;i++){
            int c = tid + i*256;
            int k=c>>5, nc=(c&31)*4;
            cp16(sB + (uint32_t)(k*B1_ST+nc)*4u,
                 B + (size_t)(kt*T1K+k)*H_DIM + nBase + nc);
        }
    };

    issue(0,0); cp_commit();
    issue(1,1); cp_commit();

    const int warp = tid>>5, lane = tid&31;
    const int wm = warp & 3, wn = warp >> 2;
    const int gid = lane>>2, t4 = lane&3;

    float acc[2][8][4];
#pragma unroll
    for (int mi=0;mi<2;mi++)
#pragma unroll
        for(int ni=0;ni<8;ni++)
#pragma unroll
            for(int q=0;q<4;q++) acc[mi][ni][q]=0.f;

    const int aRow0 = wm*32 + gid;
    const int bCol0 = wn*64 + gid;

    for (int kt=0; kt<KT; kt++){
        asm volatile("cp.async.wait_group %0;\n"::"n"(STG1-2));
        __syncthreads();
        if (kt + (STG1-1) < KT) issue(kt+STG1-1, (kt+STG1-1)%STG1);
        cp_commit();

        const uint32_t* uA = (const uint32_t*)(smem + (kt%STG1)*STAGE1_FL);
        const uint32_t* uB = uA + A1_FL;
#pragma unroll
        for (int kk=0; kk<T1K; kk+=8){
            uint32_t a[2][4], b[8][2];
#pragma unroll
            for (int mi=0;mi<2;mi++){
                int r0 = (aRow0 + mi*16)*A1_ST + kk + t4;
                a[mi][0]=uA[r0];
                a[mi][1]=uA[r0+8*A1_ST];
                a[mi][2]=uA[r0+4];
                a[mi][3]=uA[r0+8*A1_ST+4];
            }
#pragma unroll
            for (int ni=0;ni<8;ni++){
                int c0 = (kk+t4)*B1_ST + bCol0 + ni*8;
                b[ni][0]=uB[c0]; b[ni][1]=uB[c0+4*B1_ST];
            }
#pragma unroll
            for (int mi=0;mi<2;mi++)
#pragma unroll
                for (int ni=0;ni<8;ni++)
                    mma_tf32(acc[mi][ni], a[mi][0],a[mi][1],a[mi][2],a[mi][3],
                             b[ni][0],b[ni][1]);
        }
    }
    asm volatile("cp.async.wait_group 0;\n");

    const int epiRow = mBase + wm*32 + gid;
    const int epiCol = nBase + wn*64 + t4*2;
#pragma unroll
    for (int mi=0;mi<2;mi++){
#pragma unroll
        for (int half=0; half<2; half++){
            int r = epiRow + mi*16 + half*8;
            size_t rowOff = (size_t)(r*E_DIM + z)*(size_t)H_DIM;
#pragma unroll
            for (int ni=0;ni<8;ni++){
                int col = epiCol + ni*8;
                __half2 p = __floats2half2_rn(acc[mi][ni][half*2+0],
                                              acc[mi][ni][half*2+1]);
                *(__half2*)(C + rowOff + col) = p;
            }
        }
    }
}

// ---------------- GEMM2: fp16 m16n8k16 f32-acc, TK=64, ldmatrix --------------
// Cexp[r][v] = exp( sum_k A[r][k] * B[v][k] ); g_Z[r] += row partials.
// Smem rows: 128 B data + 16 B pad = 144 B = 36 words (≡4 mod 32 -> each 8-row
// 16 B ldmatrix phase covers 8 distinct 4-bank groups: conflict-free).
#define TM 256
#define TN 128
#define TK2 64
#define STAGES 3
#define A2_ST 36               // words per smem row
#define A_W (TM*A2_ST)         // 9216 words
#define B_W (TN*A2_ST)         // 4608 words
#define STAGE_W (A_W + B_W)    // 13824 words
#define A_BYTES (A_W*4)        // 36864
#define SMEM2_BYTES (STAGE_W*STAGES*4)   // 165888 B

__device__ __forceinline__ void mma_f16(float c[4], uint32_t a0,uint32_t a1,uint32_t a2,uint32_t a3,
                                        uint32_t b0,uint32_t b1){
    asm volatile("mma.sync.aligned.m16n8k16.row.col.f32.f16.f16.f32 "
        "{%0,%1,%2,%3},{%4,%5,%6,%7},{%8,%9},{%0,%1,%2,%3};\n"
        : "+f"(c[0]),"+f"(c[1]),"+f"(c[2]),"+f"(c[3])
        : "r"(a0),"r"(a1),"r"(a2),"r"(a3),"r"(b0),"r"(b1));
}

__global__ __launch_bounds__(256)
void gemm2_f16_kernel(const __half* __restrict__ A,
                      const __half* __restrict__ B,
                      __half* __restrict__ Cexp, int Ntot)
{
    extern __shared__ uint32_t smw[];
    const int tid = threadIdx.x;
    const int mBase = blockIdx.x*TM, nBase = blockIdx.y*TN;
    const uint32_t sbase = (uint32_t)__cvta_generic_to_shared(smw);
    const int KT = H_DIM/TK2;   // 40

    auto issue = [&](int kt, int st){
        uint32_t sA = sbase + (uint32_t)(st*STAGE_W)*4u;
        uint32_t sB = sA + (uint32_t)A_BYTES;
        // A: 256 rows x 128 B -> 2048 chunks of 16B, 8/thread
#pragma unroll
        for (int i=0;i<8;i++){
            int c = tid + i*256;
            int row = c>>3, ch = c&7;
            cp16(sA + (uint32_t)(row*144 + ch*16),
                 A + (size_t)(mBase+row)*H_DIM + kt*TK2 + ch*8);
        }
        // B: 128 rows x 128 B -> 1024 chunks, 4/thread
#pragma unroll
        for (int i=0;i<4;i++){
            int c = tid + i*256;
            int row = c>>3, ch = c&7;
            cp16(sB + (uint32_t)(row*144 + ch*16),
                 B + (size_t)(nBase+row)*H_DIM + kt*TK2 + ch*8);
        }
    };

    issue(0,0); cp_commit();
    issue(1,1); cp_commit();

    const int warp = tid>>5, lane = tid&31;
    const int wm = warp & 3, wn = warp >> 2;    // 4x2 warps, 64x64 each
    const int gid = lane>>2, t4 = lane&3;

    // ldmatrix lane-address precompute (byte offsets within one stage)
    const int m8   = lane >> 3;      // quadrant 0..3
    const int lrow = lane & 7;       // row within 8-row group
    uint32_t aOff[4], bOff[4];
#pragma unroll
    for (int mi=0;mi<4;mi++){
        // A quadrants: m0=(r0-7,k0-7) m1=(r8-15,k0-7) m2=(r0-7,k8-15) m3=(r8-15,k8-15)
        int row = wm*64 + mi*16 + (m8 & 1)*8 + lrow;
        aOff[mi] = (uint32_t)(row*144 + (m8 >> 1)*16);
    }
#pragma unroll
    for (int pr=0;pr<4;pr++){
        // B quadrants: m0=(n0-7,k0-7) m1=(n0-7,k8-15) m2=(n8-15,k0-7) m3=(n8-15,k8-15)
        int row = wn*64 + pr*16 + (m8 >> 1)*8 + lrow;
        bOff[pr] = (uint32_t)(A_BYTES + row*144 + (m8 & 1)*16);
    }

    float acc[4][8][4];
#pragma unroll
    for (int mi=0;mi<4;mi++)
#pragma unroll
        for(int ni=0;ni<8;ni++)
#pragma unroll
            for(int q=0;q<4;q++) acc[mi][ni][q]=0.f;

    for (int kt=0; kt<KT; kt++){
        asm volatile("cp.async.wait_group %0;\n"::"n"(STAGES-2));
        __syncthreads();
        if (kt + (STAGES-1) < KT) issue(kt+STAGES-1, (kt+STAGES-1)%STAGES);
        cp_commit();

        const uint32_t stAddr = sbase + (uint32_t)((kt%STAGES)*STAGE_W)*4u;
#pragma unroll
        for (int k4=0; k4<4; k4++){            // four k16 steps per TK2=64
            const uint32_t kb = stAddr + (uint32_t)(k4*32);   // +16 halves
            uint32_t a[4][4], b[8][2];
#pragma unroll
            for (int mi=0;mi<4;mi++)
                LDSM4(a[mi][0], a[mi][1], a[mi][2], a[mi][3], kb + aOff[mi]);
#pragma unroll
            for (int pr=0;pr<4;pr++)
                LDSM4(b[2*pr][0], b[2*pr][1], b[2*pr+1][0], b[2*pr+1][1], kb + bOff[pr]);
#pragma unroll
            for (int mi=0;mi<4;mi++)
#pragma unroll
                for (int ni=0;ni<8;ni++)
                    mma_f16(acc[mi][ni], a[mi][0],a[mi][1],a[mi][2],a[mi][3],
                            b[ni][0],b[ni][1]);
        }
    }
    asm volatile("cp.async.wait_group 0;\n");

    // epilogue: exp + fp16 store + fused row-sum
    const int epiRow = mBase + wm*64 + gid;
    const int epiCol = nBase + wn*64 + t4*2;
#pragma unroll
    for (int mi=0;mi<4;mi++){
#pragma unroll
        for (int half=0; half<2; half++){
            int r = epiRow + mi*16 + half*8;
            size_t rowOff = (size_t)r*(size_t)LDE;
            float rsum = 0.f;
#pragma unroll
            for (int ni=0;ni<8;ni++){
                int col = epiCol + ni*8;
                float v0 = __expf(acc[mi][ni][half*2+0]);
                float v1 = __expf(acc[mi][ni][half*2+1]);
                if (col+1 < Ntot){
                    *(__half2*)(Cexp + rowOff + col) = __floats2half2_rn(v0, v1);
                    rsum += v0 + v1;
                } else if (col < Ntot){
                    Cexp[rowOff+col] = __float2half_rn(v0);
                    rsum += v0;
                }
            }
            rsum += __shfl_xor_sync(0xffffffffu, rsum, 1);
            rsum += __shfl_xor_sync(0xffffffffu, rsum, 2);
            if (t4 == 0) atomicAdd(&g_Z[r], rsum);
        }
    }
}

// ---------------- final: mixture + log (half2 reads) -------------------------
__global__ void final_kernel(float* __restrict__ out){
    int s = blockIdx.y;
    int v2 = blockIdx.x*256 + threadIdx.x;       // half2 index
    __shared__ float w[E_DIM];
    if (threadIdx.x < E_DIM){
        int idx = s*E_DIM + threadIdx.x;
        w[threadIdx.x] = g_gate[idx] / g_Z[idx];
    }
    __syncthreads();
    const int NV2 = V_DIM/2;                     // 25128 full pairs
    if (v2 < NV2){
        const __half* base = g_expl + (size_t)(s*E_DIM)*LDE + 2*v2;
        float a0 = 0.f, a1 = 0.f;
#pragma unroll
        for (int e=0;e<E_DIM;e++){
            float2 p = __half22float2(*(const __half2*)(base + (size_t)e*LDE));
            a0 += w[e]*p.x; a1 += w[e]*p.y;
        }
        size_t o = (size_t)s*V_DIM + 2*v2;
        out[o]   = logf(a0 + 1e-10f);
        out[o+1] = logf(a1 + 1e-10f);
    } else if (v2 == NV2){                       // tail element v = V_DIM-1
        const __half* base = g_expl + (size_t)(s*E_DIM)*LDE + (V_DIM-1);
        float a0 = 0.f;
#pragma unroll
        for (int e=0;e<E_DIM;e++) a0 += w[e]*__half2float(base[(size_t)e*LDE]);
        out[(size_t)s*V_DIM + (V_DIM-1)] = logf(a0 + 1e-10f);
    }
}

// ---------------- launch -----------------------------------------------------
extern "C" void kernel_launch(void* const* d_in, const int* in_sizes, int n_in,
                              void* d_out, int out_size){
    const float* hid  = (const float*)d_in[0];
    const float* emb  = (const float*)d_in[1];
    const float* nsc  = (const float*)d_in[2];
    const float* expw = (const float*)d_in[3];
    const float* gw   = (const float*)d_in[4];
    float* out = (float*)d_out;

    cudaFuncSetAttribute(gemm1_tf32_kernel,
                         cudaFuncAttributeMaxDynamicSharedMemorySize, SMEM1_BYTES);
    cudaFuncSetAttribute(gemm2_f16_kernel,
                         cudaFuncAttributeMaxDynamicSharedMemorySize, SMEM2_BYTES);

    float *ph;
    __half *pehh, *pembh, *pexpl;
    cudaGetSymbolAddress((void**)&ph,    g_h);
    cudaGetSymbolAddress((void**)&pehh,  g_ehh);
    cudaGetSymbolAddress((void**)&pembh, g_embh);
    cudaGetSymbolAddress((void**)&pexpl, g_expl);

    // 1) rmsnorm + gate softmax
    prep_kernel<<<S_DIM, 256>>>(hid, nsc, gw);

    // 2) embedding -> fp16 (padded rows zeroed) ; zero Z accumulators
    embconv_kernel<<<VPAD, 256>>>(emb);
    zeroZ_kernel<<<(R_DIM+255)/256, 256>>>();

    // 3) expert_hidden (tf32, 2 CTA/SM, 3-stage), fp16 out; row r = s*E + e
    {
        dim3 g(S_DIM/T1M, H_DIM/T1N, E_DIM);   // (2, 20, 10) = 400 CTAs
        gemm1_tf32_kernel<<<g, 256, SMEM1_BYTES>>>(ph, expw, pehh);
    }

    // 4) exp(logits) fp16 tensor cores (f32 acc, TK=64, ldmatrix) + fused rowsum
    {
        dim3 g(R_DIM/TM, (V_DIM + TN - 1)/TN, 1);   // (10, 393) — M fastest for L2 B reuse
        gemm2_f16_kernel<<<g, 256, SMEM2_BYTES>>>(pehh, pembh, pexpl, V_DIM);
    }

    // 5) mixture + log
    {
        dim3 g((V_DIM/2 + 256)/256, S_DIM, 1);
        final_kernel<<<g, 256>>>(out);
    }
}

// round 16
// speedup vs baseline: 2.3705x; 1.0243x over previous
#include <cuda_runtime.h>
#include <cuda_fp16.h>
#include <cstdint>
#include <cstddef>

#define H_DIM 2560
#define S_DIM 256
#define E_DIM 10
#define V_DIM 50257
#define VPAD  50432            // 197*256 (embh row padding)
#define LDE   50304            // padded expl stride = 393*128
#define R_DIM (S_DIM*E_DIM)    // 2560

// ---------------- scratch (static device allocations) -----------------------
__device__ float g_h[S_DIM*H_DIM];
__device__ __half g_ehh[(size_t)R_DIM*H_DIM];              // GEMM1 out, fp16
__device__ __half g_embh[(size_t)VPAD*H_DIM];              // embedding fp16, padded
__device__ __half g_expl[(size_t)R_DIM*LDE];               // exp(logits), fp16
__device__ float g_Z[R_DIM];                               // row sums (atomic)
__device__ float g_gate[S_DIM*E_DIM];

__device__ __forceinline__ float tf32_rna(float x){
    uint32_t u; asm("cvt.rna.tf32.f32 %0, %1;" : "=r"(u) : "f"(x));
    return __uint_as_float(u);
}

__device__ __forceinline__ void cp16(uint32_t d, const void* s){
    asm volatile("cp.async.cg.shared.global [%0], [%1], 16;\n" :: "r"(d), "l"(s));
}
__device__ __forceinline__ void cp_commit(){ asm volatile("cp.async.commit_group;\n"); }

#define LDSM4(r0,r1,r2,r3,addr) \
    asm volatile("ldmatrix.sync.aligned.m8n8.x4.shared.b16 {%0,%1,%2,%3}, [%4];" \
        : "=r"(r0),"=r"(r1),"=r"(r2),"=r"(r3) : "r"(addr))

// ---------------- kernel 1: rmsnorm + gate softmax ---------------------------
__global__ void prep_kernel(const float* __restrict__ hid,
                            const float* __restrict__ nscale,
                            const float* __restrict__ gateW){
    int s = blockIdx.x, t = threadIdx.x;
    __shared__ float red[256];
    __shared__ float gred[E_DIM][256];
    float x[10];
    float ss = 0.f;
#pragma unroll
    for (int j=0;j<10;j++){ x[j] = hid[s*H_DIM + t + j*256]; ss += x[j]*x[j]; }
    red[t] = ss; __syncthreads();
    for (int off=128; off; off>>=1){ if(t<off) red[t]+=red[t+off]; __syncthreads(); }
    float inv = rsqrtf(red[0]/(float)H_DIM + 1e-5f);
    float ga[E_DIM];
#pragma unroll
    for(int e=0;e<E_DIM;e++) ga[e]=0.f;
#pragma unroll
    for (int j=0;j<10;j++){
        int i = t + j*256;
        float h = x[j]*inv*nscale[i];
        g_h[s*H_DIM + i] = tf32_rna(h);
#pragma unroll
        for(int e=0;e<E_DIM;e++) ga[e] += h*gateW[i*E_DIM + e];
    }
#pragma unroll
    for(int e=0;e<E_DIM;e++) gred[e][t]=ga[e];
    __syncthreads();
    for(int off=128; off; off>>=1){
        if(t<off){
#pragma unroll
            for(int e=0;e<E_DIM;e++) gred[e][t]+=gred[e][t+off];
        }
        __syncthreads();
    }
    if (t==0){
        float m=-1e30f;
#pragma unroll
        for(int e=0;e<E_DIM;e++) m=fmaxf(m,gred[e][0]);
        float sum=0.f; float ex[E_DIM];
#pragma unroll
        for(int e=0;e<E_DIM;e++){ ex[e]=expf(gred[e][0]-m); sum+=ex[e]; }
#pragma unroll
        for(int e=0;e<E_DIM;e++) g_gate[s*E_DIM+e]=ex[e]/sum;
    }
}

// ---------------- embedding fp32 -> fp16 (padded, zero tail) -----------------
__global__ void embconv_kernel(const float* __restrict__ emb){
    int row = blockIdx.x, t = threadIdx.x;
    __half2* dst = (__half2*)(g_embh + (size_t)row*H_DIM);
    if (row < V_DIM){
        const float2* src = (const float2*)(emb + (size_t)row*H_DIM);
        for (int i=t; i<H_DIM/2; i+=256){
            float2 v = src[i];
            dst[i] = __floats2half2_rn(v.x, v.y);
        }
    } else {
        for (int i=t; i<H_DIM/2; i+=256) dst[i] = __floats2half2_rn(0.f, 0.f);
    }
}

__global__ void zeroZ_kernel(){
    int i = blockIdx.x*256 + threadIdx.x;
    if (i < R_DIM) g_Z[i] = 0.f;
}

// ---------------- GEMM1: tf32 mma, TM=128, 2 CTAs/SM, 3-stage ---------------
#define T1M 128
#define T1N 128
#define T1K 32
#define STG1 3
#define A1_ST 36
#define B1_ST 132
#define A1_FL (T1M*A1_ST)          // 4608
#define B1_FL 4608                 // >= 32*132 = 4224
#define STAGE1_FL (A1_FL + B1_FL)  // 9216
#define SMEM1_BYTES (STAGE1_FL*STG1*4)  // 110592 (2 CTAs = 221 KB <= 228 KB)

__device__ __forceinline__ void mma_tf32(float c[4], uint32_t a0,uint32_t a1,uint32_t a2,uint32_t a3,
                                         uint32_t b0,uint32_t b1){
    asm volatile("mma.sync.aligned.m16n8k8.row.col.f32.tf32.tf32.f32 "
        "{%0,%1,%2,%3},{%4,%5,%6,%7},{%8,%9},{%0,%1,%2,%3};\n"
        : "+f"(c[0]),"+f"(c[1]),"+f"(c[2]),"+f"(c[3])
        : "r"(a0),"r"(a1),"r"(a2),"r"(a3),"r"(b0),"r"(b1));
}

__global__ __launch_bounds__(256, 2)
void gemm1_tf32_kernel(const float* __restrict__ A, const float* __restrict__ Bg,
                       __half* __restrict__ C)
{
    extern __shared__ float smem[];
    const int tid = threadIdx.x;
    const int mBase = blockIdx.x*T1M, nBase = blockIdx.y*T1N;
    const int z = blockIdx.z;
    const float* B = Bg + (size_t)z*(size_t)H_DIM*H_DIM;
    const uint32_t sbase = (uint32_t)__cvta_generic_to_shared(smem);
    const int KT = H_DIM/T1K;   // 80

    auto issue = [&](int kt, int st){
        uint32_t sA = sbase + (uint32_t)(st*STAGE1_FL)*4u;
        uint32_t sB = sA + (uint32_t)A1_FL*4u;
#pragma unroll
        for (int i=0;i<4;i++){
            int c = tid + i*256;
            int row = c>>3, kc=(c&7)*4;
            cp16(sA + (uint32_t)(row*A1_ST+kc)*4u,
                 A + (size_t)(mBase+row)*H_DIM + kt*T1K + kc);
        }
#pragma unroll
        for (int i=0;i<4;i++){
            int c = tid + i*256;
            int k=c>>5, nc=(c&31)*4;
            cp16(sB + (uint32_t)(k*B1_ST+nc)*4u,
                 B + (size_t)(kt*T1K+k)*H_DIM + nBase + nc);
        }
    };

    issue(0,0); cp_commit();
    issue(1,1); cp_commit();

    const int warp = tid>>5, lane = tid&31;
    const int wm = warp & 3, wn = warp >> 2;
    const int gid = lane>>2, t4 = lane&3;

    float acc[2][8][4];
#pragma unroll
    for (int mi=0;mi<2;mi++)
#pragma unroll
        for(int ni=0;ni<8;ni++)
#pragma unroll
            for(int q=0;q<4;q++) acc[mi][ni][q]=0.f;

    const int aRow0 = wm*32 + gid;
    const int bCol0 = wn*64 + gid;

    for (int kt=0; kt<KT; kt++){
        asm volatile("cp.async.wait_group %0;\n"::"n"(STG1-2));
        __syncthreads();
        if (kt + (STG1-1) < KT) issue(kt+STG1-1, (kt+STG1-1)%STG1);
        cp_commit();

        const uint32_t* uA = (const uint32_t*)(smem + (kt%STG1)*STAGE1_FL);
        const uint32_t* uB = uA + A1_FL;
#pragma unroll
        for (int kk=0; kk<T1K; kk+=8){
            uint32_t a[2][4], b[8][2];
#pragma unroll
            for (int mi=0;mi<2;mi++){
                int r0 = (aRow0 + mi*16)*A1_ST + kk + t4;
                a[mi][0]=uA[r0];
                a[mi][1]=uA[r0+8*A1_ST];
                a[mi][2]=uA[r0+4];
                a[mi][3]=uA[r0+8*A1_ST+4];
            }
#pragma unroll
            for (int ni=0;ni<8;ni++){
                int c0 = (kk+t4)*B1_ST + bCol0 + ni*8;
                b[ni][0]=uB[c0]; b[ni][1]=uB[c0+4*B1_ST];
            }
#pragma unroll
            for (int mi=0;mi<2;mi++)
#pragma unroll
                for (int ni=0;ni<8;ni++)
                    mma_tf32(acc[mi][ni], a[mi][0],a[mi][1],a[mi][2],a[mi][3],
                             b[ni][0],b[ni][1]);
        }
    }
    asm volatile("cp.async.wait_group 0;\n");

    const int epiRow = mBase + wm*32 + gid;
    const int epiCol = nBase + wn*64 + t4*2;
#pragma unroll
    for (int mi=0;mi<2;mi++){
#pragma unroll
        for (int half=0; half<2; half++){
            int r = epiRow + mi*16 + half*8;
            size_t rowOff = (size_t)(r*E_DIM + z)*(size_t)H_DIM;
#pragma unroll
            for (int ni=0;ni<8;ni++){
                int col = epiCol + ni*8;
                __half2 p = __floats2half2_rn(acc[mi][ni][half*2+0],
                                              acc[mi][ni][half*2+1]);
                *(__half2*)(C + rowOff + col) = p;
            }
        }
    }
}

// ---------------- GEMM2: fp16 m16n8k16 f32-acc, TK=128, 2-stage, ldmatrix ----
// Cexp[r][v] = exp( sum_k A[r][k] * B[v][k] ); g_Z[r] += row partials.
// Smem rows: 256 B data + 16 B pad = 272 B = 68 words (68 = 4 mod 32 -> same
// conflict-free proof as the 36-word layout: 8-row ldmatrix phases cover all
// 32 banks).
#define TM 256
#define TN 128
#define TK2 128
#define STAGES 2
#define A2_ST 68               // words per smem row
#define ROWB 272               // bytes per smem row
#define A_W (TM*A2_ST)         // 17408 words
#define B_W (TN*A2_ST)         // 8704 words
#define STAGE_W (A_W + B_W)    // 26112 words
#define A_BYTES (A_W*4)        // 69632
#define SMEM2_BYTES (STAGE_W*STAGES*4)   // 208896 B

__device__ __forceinline__ void mma_f16(float c[4], uint32_t a0,uint32_t a1,uint32_t a2,uint32_t a3,
                                        uint32_t b0,uint32_t b1){
    asm volatile("mma.sync.aligned.m16n8k16.row.col.f32.f16.f16.f32 "
        "{%0,%1,%2,%3},{%4,%5,%6,%7},{%8,%9},{%0,%1,%2,%3};\n"
        : "+f"(c[0]),"+f"(c[1]),"+f"(c[2]),"+f"(c[3])
        : "r"(a0),"r"(a1),"r"(a2),"r"(a3),"r"(b0),"r"(b1));
}

__global__ __launch_bounds__(256)
void gemm2_f16_kernel(const __half* __restrict__ A,
                      const __half* __restrict__ B,
                      __half* __restrict__ Cexp, int Ntot)
{
    extern __shared__ uint32_t smw[];
    const int tid = threadIdx.x;
    const int mBase = blockIdx.x*TM, nBase = blockIdx.y*TN;
    const uint32_t sbase = (uint32_t)__cvta_generic_to_shared(smw);
    const int KT = H_DIM/TK2;   // 20

    auto issue = [&](int kt, int st){
        uint32_t sA = sbase + (uint32_t)(st*STAGE_W)*4u;
        uint32_t sB = sA + (uint32_t)A_BYTES;
        // A: 256 rows x 256 B -> 4096 chunks of 16B, 16/thread
#pragma unroll
        for (int i=0;i<16;i++){
            int c = tid + i*256;
            int row = c>>4, ch = c&15;
            cp16(sA + (uint32_t)(row*ROWB + ch*16),
                 A + (size_t)(mBase+row)*H_DIM + kt*TK2 + ch*8);
        }
        // B: 128 rows x 256 B -> 2048 chunks, 8/thread
#pragma unroll
        for (int i=0;i<8;i++){
            int c = tid + i*256;
            int row = c>>4, ch = c&15;
            cp16(sB + (uint32_t)(row*ROWB + ch*16),
                 B + (size_t)(nBase+row)*H_DIM + kt*TK2 + ch*8);
        }
    };

    issue(0,0); cp_commit();

    const int warp = tid>>5, lane = tid&31;
    const int wm = warp & 3, wn = warp >> 2;    // 4x2 warps, 64x64 each
    const int gid = lane>>2, t4 = lane&3;

    // ldmatrix lane-address precompute (byte offsets within one stage)
    const int m8   = lane >> 3;      // quadrant 0..3
    const int lrow = lane & 7;       // row within 8-row group
    uint32_t aOff[4], bOff[4];
#pragma unroll
    for (int mi=0;mi<4;mi++){
        // A quadrants: m0=(r0-7,k0-7) m1=(r8-15,k0-7) m2=(r0-7,k8-15) m3=(r8-15,k8-15)
        int row = wm*64 + mi*16 + (m8 & 1)*8 + lrow;
        aOff[mi] = (uint32_t)(row*ROWB + (m8 >> 1)*16);
    }
#pragma unroll
    for (int pr=0;pr<4;pr++){
        // B quadrants: m0=(n0-7,k0-7) m1=(n0-7,k8-15) m2=(n8-15,k0-7) m3=(n8-15,k8-15)
        int row = wn*64 + pr*16 + (m8 >> 1)*8 + lrow;
        bOff[pr] = (uint32_t)(A_BYTES + row*ROWB + (m8 & 1)*16);
    }

    float acc[4][8][4];
#pragma unroll
    for (int mi=0;mi<4;mi++)
#pragma unroll
        for(int ni=0;ni<8;ni++)
#pragma unroll
            for(int q=0;q<4;q++) acc[mi][ni][q]=0.f;

    for (int kt=0; kt<KT; kt++){
        __syncthreads();                           // prior compute done with stage (kt+1)&1
        if (kt+1 < KT) issue(kt+1, (kt+1)&1);
        cp_commit();
        asm volatile("cp.async.wait_group 1;\n");  // stage kt ready (kt+1 may remain)
        __syncthreads();

        const uint32_t stAddr = sbase + (uint32_t)((kt&1)*STAGE_W)*4u;
#pragma unroll
        for (int k4=0; k4<8; k4++){            // eight k16 steps per TK2=128
            const uint32_t kb = stAddr + (uint32_t)(k4*32);   // +16 halves
            uint32_t a[4][4], b[8][2];
#pragma unroll
            for (int mi=0;mi<4;mi++)
                LDSM4(a[mi][0], a[mi][1], a[mi][2], a[mi][3], kb + aOff[mi]);
#pragma unroll
            for (int pr=0;pr<4;pr++)
                LDSM4(b[2*pr][0], b[2*pr][1], b[2*pr+1][0], b[2*pr+1][1], kb + bOff[pr]);
#pragma unroll
            for (int mi=0;mi<4;mi++)
#pragma unroll
                for (int ni=0;ni<8;ni++)
                    mma_f16(acc[mi][ni], a[mi][0],a[mi][1],a[mi][2],a[mi][3],
                            b[ni][0],b[ni][1]);
        }
    }
    asm volatile("cp.async.wait_group 0;\n");

    // epilogue: exp + fp16 store + fused row-sum
    const int epiRow = mBase + wm*64 + gid;
    const int epiCol = nBase + wn*64 + t4*2;
#pragma unroll
    for (int mi=0;mi<4;mi++){
#pragma unroll
        for (int half=0; half<2; half++){
            int r = epiRow + mi*16 + half*8;
            size_t rowOff = (size_t)r*(size_t)LDE;
            float rsum = 0.f;
#pragma unroll
            for (int ni=0;ni<8;ni++){
                int col = epiCol + ni*8;
                float v0 = __expf(acc[mi][ni][half*2+0]);
                float v1 = __expf(acc[mi][ni][half*2+1]);
                if (col+1 < Ntot){
                    *(__half2*)(Cexp + rowOff + col) = __floats2half2_rn(v0, v1);
                    rsum += v0 + v1;
                } else if (col < Ntot){
                    Cexp[rowOff+col] = __float2half_rn(v0);
                    rsum += v0;
                }
            }
            rsum += __shfl_xor_sync(0xffffffffu, rsum, 1);
            rsum += __shfl_xor_sync(0xffffffffu, rsum, 2);
            if (t4 == 0) atomicAdd(&g_Z[r], rsum);
        }
    }
}

// ---------------- final: mixture + log (half2 reads) -------------------------
__global__ void final_kernel(float* __restrict__ out){
    int s = blockIdx.y;
    int v2 = blockIdx.x*256 + threadIdx.x;       // half2 index
    __shared__ float w[E_DIM];
    if (threadIdx.x < E_DIM){
        int idx = s*E_DIM + threadIdx.x;
        w[threadIdx.x] = g_gate[idx] / g_Z[idx];
    }
    __syncthreads();
    const int NV2 = V_DIM/2;                     // 25128 full pairs
    if (v2 < NV2){
        const __half* base = g_expl + (size_t)(s*E_DIM)*LDE + 2*v2;
        float a0 = 0.f, a1 = 0.f;
#pragma unroll
        for (int e=0;e<E_DIM;e++){
            float2 p = __half22float2(*(const __half2*)(base + (size_t)e*LDE));
            a0 += w[e]*p.x; a1 += w[e]*p.y;
        }
        size_t o = (size_t)s*V_DIM + 2*v2;
        out[o]   = logf(a0 + 1e-10f);
        out[o+1] = logf(a1 + 1e-10f);
    } else if (v2 == NV2){                       // tail element v = V_DIM-1
        const __half* base = g_expl + (size_t)(s*E_DIM)*LDE + (V_DIM-1);
        float a0 = 0.f;
#pragma unroll
        for (int e=0;e<E_DIM;e++) a0 += w[e]*__half2float(base[(size_t)e*LDE]);
        out[(size_t)s*V_DIM + (V_DIM-1)] = logf(a0 + 1e-10f);
    }
}

// ---------------- launch -----------------------------------------------------
extern "C" void kernel_launch(void* const* d_in, const int* in_sizes, int n_in,
                              void* d_out, int out_size){
    const float* hid  = (const float*)d_in[0];
    const float* emb  = (const float*)d_in[1];
    const float* nsc  = (const float*)d_in[2];
    const float* expw = (const float*)d_in[3];
    const float* gw   = (const float*)d_in[4];
    float* out = (float*)d_out;

    cudaFuncSetAttribute(gemm1_tf32_kernel,
                         cudaFuncAttributeMaxDynamicSharedMemorySize, SMEM1_BYTES);
    cudaFuncSetAttribute(gemm2_f16_kernel,
                         cudaFuncAttributeMaxDynamicSharedMemorySize, SMEM2_BYTES);

    float *ph;
    __half *pehh, *pembh, *pexpl;
    cudaGetSymbolAddress((void**)&ph,    g_h);
    cudaGetSymbolAddress((void**)&pehh,  g_ehh);
    cudaGetSymbolAddress((void**)&pembh, g_embh);
    cudaGetSymbolAddress((void**)&pexpl, g_expl);

    // 1) rmsnorm + gate softmax
    prep_kernel<<<S_DIM, 256>>>(hid, nsc, gw);

    // 2) embedding -> fp16 (padded rows zeroed) ; zero Z accumulators
    embconv_kernel<<<VPAD, 256>>>(emb);
    zeroZ_kernel<<<(R_DIM+255)/256, 256>>>();

    // 3) expert_hidden (tf32, 2 CTA/SM, 3-stage), fp16 out; row r = s*E + e
    {
        dim3 g(S_DIM/T1M, H_DIM/T1N, E_DIM);   // (2, 20, 10) = 400 CTAs
        gemm1_tf32_kernel<<<g, 256, SMEM1_BYTES>>>(ph, expw, pehh);
    }

    // 4) exp(logits) fp16 tensor cores (f32 acc, TK=128, 2-stage, ldmatrix)
    {
        dim3 g(R_DIM/TM, (V_DIM + TN - 1)/TN, 1);   // (10, 393) — M fastest for L2 B reuse
        gemm2_f16_kernel<<<g, 256, SMEM2_BYTES>>>(pehh, pembh, pexpl, V_DIM);
    }

    // 5) mixture + log
    {
        dim3 g((V_DIM/2 + 256)/256, S_DIM, 1);
        final_kernel<<<g, 256>>>(out);
    }
}

// round 17
// speedup vs baseline: 2.4341x; 1.0268x over previous
#include <cuda_runtime.h>
#include <cuda_fp16.h>
#include <cstdint>
#include <cstddef>

#define H_DIM 2560
#define S_DIM 256
#define E_DIM 10
#define V_DIM 50257
#define VPAD  50432            // 197*256 (embh row padding)
#define LDE   50304            // padded expl stride = 393*128
#define R_DIM (S_DIM*E_DIM)    // 2560

// ---------------- scratch (static device allocations) -----------------------
__device__ __half g_hh[S_DIM*H_DIM];                       // rmsnorm out, fp16
__device__ __half g_wh[(size_t)E_DIM*H_DIM*H_DIM];         // weights fp16, [e][n][k]
__device__ __half g_ehh[(size_t)R_DIM*H_DIM];              // GEMM1 out, fp16
__device__ __half g_embh[(size_t)VPAD*H_DIM];              // embedding fp16, padded
__device__ __half g_expl[(size_t)R_DIM*LDE];               // exp(logits), fp16
__device__ float g_Z[R_DIM];                               // row sums (atomic)
__device__ float g_gate[S_DIM*E_DIM];

__device__ __forceinline__ void cp16(uint32_t d, const void* s){
    asm volatile("cp.async.cg.shared.global [%0], [%1], 16;\n" :: "r"(d), "l"(s));
}
__device__ __forceinline__ void cp_commit(){ asm volatile("cp.async.commit_group;\n"); }

#define LDSM4(r0,r1,r2,r3,addr) \
    asm volatile("ldmatrix.sync.aligned.m8n8.x4.shared.b16 {%0,%1,%2,%3}, [%4];" \
        : "=r"(r0),"=r"(r1),"=r"(r2),"=r"(r3) : "r"(addr))

__device__ __forceinline__ void mma_f16(float c[4], uint32_t a0,uint32_t a1,uint32_t a2,uint32_t a3,
                                        uint32_t b0,uint32_t b1){
    asm volatile("mma.sync.aligned.m16n8k16.row.col.f32.f16.f16.f32 "
        "{%0,%1,%2,%3},{%4,%5,%6,%7},{%8,%9},{%0,%1,%2,%3};\n"
        : "+f"(c[0]),"+f"(c[1]),"+f"(c[2]),"+f"(c[3])
        : "r"(a0),"r"(a1),"r"(a2),"r"(a3),"r"(b0),"r"(b1));
}

// ---------------- kernel 1: rmsnorm + gate softmax + zero Z ------------------
__global__ void prep_kernel(const float* __restrict__ hid,
                            const float* __restrict__ nscale,
                            const float* __restrict__ gateW){
    int s = blockIdx.x, t = threadIdx.x;
    __shared__ float red[256];
    __shared__ float gred[E_DIM][256];
    float x[10];
    float ss = 0.f;
#pragma unroll
    for (int j=0;j<10;j++){ x[j] = hid[s*H_DIM + t + j*256]; ss += x[j]*x[j]; }
    red[t] = ss; __syncthreads();
    for (int off=128; off; off>>=1){ if(t<off) red[t]+=red[t+off]; __syncthreads(); }
    float inv = rsqrtf(red[0]/(float)H_DIM + 1e-5f);
    float ga[E_DIM];
#pragma unroll
    for(int e=0;e<E_DIM;e++) ga[e]=0.f;
#pragma unroll
    for (int j=0;j<10;j++){
        int i = t + j*256;
        float h = x[j]*inv*nscale[i];
        g_hh[s*H_DIM + i] = __float2half_rn(h);
#pragma unroll
        for(int e=0;e<E_DIM;e++) ga[e] += h*gateW[i*E_DIM + e];
    }
#pragma unroll
    for(int e=0;e<E_DIM;e++) gred[e][t]=ga[e];
    __syncthreads();
    for(int off=128; off; off>>=1){
        if(t<off){
#pragma unroll
            for(int e=0;e<E_DIM;e++) gred[e][t]+=gred[e][t+off];
        }
        __syncthreads();
    }
    if (t==0){
        float m=-1e30f;
#pragma unroll
        for(int e=0;e<E_DIM;e++) m=fmaxf(m,gred[e][0]);
        float sum=0.f; float ex[E_DIM];
#pragma unroll
        for(int e=0;e<E_DIM;e++){ ex[e]=expf(gred[e][0]-m); sum+=ex[e]; }
#pragma unroll
        for(int e=0;e<E_DIM;e++) g_gate[s*E_DIM+e]=ex[e]/sum;
    }
    if (t < E_DIM) g_Z[s*E_DIM + t] = 0.f;
}

// ---------------- embedding fp32 -> fp16 (padded, zero tail) -----------------
__global__ void embconv_kernel(const float* __restrict__ emb){
    int row = blockIdx.x, t = threadIdx.x;
    __half2* dst = (__half2*)(g_embh + (size_t)row*H_DIM);
    if (row < V_DIM){
        const float2* src = (const float2*)(emb + (size_t)row*H_DIM);
        for (int i=t; i<H_DIM/2; i+=256){
            float2 v = src[i];
            dst[i] = __floats2half2_rn(v.x, v.y);
        }
    } else {
        for (int i=t; i<H_DIM/2; i+=256) dst[i] = __floats2half2_rn(0.f, 0.f);
    }
}

// ---------------- weights fp32 [e][k][n] -> fp16 [e][n][k] (transpose) -------
__global__ void wconvT_kernel(const float* __restrict__ w){
    __shared__ float tile[32][33];
    int k0 = blockIdx.x*32, n0 = blockIdx.y*32, e = blockIdx.z;
    int tx = threadIdx.x & 31, ty = threadIdx.x >> 5;   // 32 x 8
    const float* src = w + (size_t)e*H_DIM*H_DIM;
    __half* dst = g_wh + (size_t)e*H_DIM*H_DIM;
#pragma unroll
    for (int j=0;j<4;j++)
        tile[ty + j*8][tx] = src[(size_t)(k0 + ty + j*8)*H_DIM + n0 + tx];
    __syncthreads();
#pragma unroll
    for (int j=0;j<4;j++)
        dst[(size_t)(n0 + ty + j*8)*H_DIM + k0 + tx] =
            __float2half_rn(tile[tx][ty + j*8]);
}

// ---------------- GEMM1: fp16 m16n8k16, TM=128, TK=64, 3-stage, ldmatrix -----
// C[(s*E+e)][n] = sum_k h[s][k] * W_e^T[n][k]; A=g_hh, B=g_wh (both K-major).
#define T1M 128
#define T1N 128
#define T1K 64
#define STG1 3
#define ROWB1 144                    // 128 B data + 16 B pad
#define A1_BYTES (T1M*ROWB1)         // 18432
#define STAGE1_B (2*A1_BYTES)        // A+B rows both 128: 36864
#define SMEM1_BYTES (STAGE1_B*STG1)  // 110592 (2 CTAs/SM)

__global__ __launch_bounds__(256, 2)
void gemm1_f16_kernel(const __half* __restrict__ A, const __half* __restrict__ Bg,
                      __half* __restrict__ C)
{
    extern __shared__ uint32_t smw1[];
    const int tid = threadIdx.x;
    const int mBase = blockIdx.x*T1M, nBase = blockIdx.y*T1N;
    const int z = blockIdx.z;
    const __half* B = Bg + (size_t)z*(size_t)H_DIM*H_DIM;
    const uint32_t sbase = (uint32_t)__cvta_generic_to_shared(smw1);
    const int KT = H_DIM/T1K;   // 40

    auto issue = [&](int kt, int st){
        uint32_t sA = sbase + (uint32_t)(st*STAGE1_B);
        uint32_t sB = sA + (uint32_t)A1_BYTES;
        // A: 128 rows x 128 B -> 1024 chunks of 16B, 4/thread
#pragma unroll
        for (int i=0;i<4;i++){
            int c = tid + i*256;
            int row = c>>3, ch = c&7;
            cp16(sA + (uint32_t)(row*ROWB1 + ch*16),
                 A + (size_t)(mBase+row)*H_DIM + kt*T1K + ch*8);
        }
        // B: 128 rows x 128 B -> 1024 chunks, 4/thread
#pragma unroll
        for (int i=0;i<4;i++){
            int c = tid + i*256;
            int row = c>>3, ch = c&7;
            cp16(sB + (uint32_t)(row*ROWB1 + ch*16),
                 B + (size_t)(nBase+row)*H_DIM + kt*T1K + ch*8);
        }
    };

    issue(0,0); cp_commit();
    issue(1,1); cp_commit();

    const int warp = tid>>5, lane = tid&31;
    const int wm = warp & 3, wn = warp >> 2;    // 4 m-warps (32 rows) x 2 n-warps (64 cols)
    const int gid = lane>>2, t4 = lane&3;

    const int m8   = lane >> 3;
    const int lrow = lane & 7;
    uint32_t aOff[2], bOff[4];
#pragma unroll
    for (int mi=0;mi<2;mi++){
        int row = wm*32 + mi*16 + (m8 & 1)*8 + lrow;
        aOff[mi] = (uint32_t)(row*ROWB1 + (m8 >> 1)*16);
    }
#pragma unroll
    for (int pr=0;pr<4;pr++){
        int row = wn*64 + pr*16 + (m8 >> 1)*8 + lrow;
        bOff[pr] = (uint32_t)(A1_BYTES + row*ROWB1 + (m8 & 1)*16);
    }

    float acc[2][8][4];
#pragma unroll
    for (int mi=0;mi<2;mi++)
#pragma unroll
        for(int ni=0;ni<8;ni++)
#pragma unroll
            for(int q=0;q<4;q++) acc[mi][ni][q]=0.f;

    for (int kt=0; kt<KT; kt++){
        asm volatile("cp.async.wait_group %0;\n"::"n"(STG1-2));
        __syncthreads();
        if (kt + (STG1-1) < KT) issue(kt+STG1-1, (kt+STG1-1)%STG1);
        cp_commit();

        const uint32_t stAddr = sbase + (uint32_t)((kt%STG1)*STAGE1_B);
#pragma unroll
        for (int k4=0; k4<4; k4++){
            const uint32_t kb = stAddr + (uint32_t)(k4*32);
            uint32_t a[2][4], b[8][2];
#pragma unroll
            for (int mi=0;mi<2;mi++)
                LDSM4(a[mi][0], a[mi][1], a[mi][2], a[mi][3], kb + aOff[mi]);
#pragma unroll
            for (int pr=0;pr<4;pr++)
                LDSM4(b[2*pr][0], b[2*pr][1], b[2*pr+1][0], b[2*pr+1][1], kb + bOff[pr]);
#pragma unroll
            for (int mi=0;mi<2;mi++)
#pragma unroll
                for (int ni=0;ni<8;ni++)
                    mma_f16(acc[mi][ni], a[mi][0],a[mi][1],a[mi][2],a[mi][3],
                            b[ni][0],b[ni][1]);
        }
    }
    asm volatile("cp.async.wait_group 0;\n");

    const int epiRow = mBase + wm*32 + gid;
    const int epiCol = nBase + wn*64 + t4*2;
#pragma unroll
    for (int mi=0;mi<2;mi++){
#pragma unroll
        for (int half=0; half<2; half++){
            int r = epiRow + mi*16 + half*8;
            size_t rowOff = (size_t)(r*E_DIM + z)*(size_t)H_DIM;
#pragma unroll
            for (int ni=0;ni<8;ni++){
                int col = epiCol + ni*8;
                __half2 p;
                p.x = __float2half_rn(acc[mi][ni][half*2+0]);
                p.y = __float2half_rn(acc[mi][ni][half*2+1]);
                *(__half2*)(C + rowOff + col) = p;
            }
        }
    }
}

// ---------------- GEMM2: fp16 m16n8k16 f32-acc, TK=128, 2-stage, ldmatrix ----
// (unchanged from R16 winner)
#define TM 256
#define TN 128
#define TK2 128
#define STAGES 2
#define ROWB 272               // 256 B data + 16 B pad
#define A_W (TM*68)
#define B_W (TN*68)
#define STAGE_W (A_W + B_W)
#define A_BYTES (A_W*4)        // 69632
#define SMEM2_BYTES (STAGE_W*STAGES*4)   // 208896 B

__global__ __launch_bounds__(256)
void gemm2_f16_kernel(const __half* __restrict__ A,
                      const __half* __restrict__ B,
                      __half* __restrict__ Cexp, int Ntot)
{
    extern __shared__ uint32_t smw[];
    const int tid = threadIdx.x;
    const int mBase = blockIdx.x*TM, nBase = blockIdx.y*TN;
    const uint32_t sbase = (uint32_t)__cvta_generic_to_shared(smw);
    const int KT = H_DIM/TK2;   // 20

    auto issue = [&](int kt, int st){
        uint32_t sA = sbase + (uint32_t)(st*STAGE_W)*4u;
        uint32_t sB = sA + (uint32_t)A_BYTES;
#pragma unroll
        for (int i=0;i<16;i++){
            int c = tid + i*256;
            int row = c>>4, ch = c&15;
            cp16(sA + (uint32_t)(row*ROWB + ch*16),
                 A + (size_t)(mBase+row)*H_DIM + kt*TK2 + ch*8);
        }
#pragma unroll
        for (int i=0;i<8;i++){
            int c = tid + i*256;
            int row = c>>4, ch = c&15;
            cp16(sB + (uint32_t)(row*ROWB + ch*16),
                 B + (size_t)(nBase+row)*H_DIM + kt*TK2 + ch*8);
        }
    };

    issue(0,0); cp_commit();

    const int warp = tid>>5, lane = tid&31;
    const int wm = warp & 3, wn = warp >> 2;
    const int gid = lane>>2, t4 = lane&3;

    const int m8   = lane >> 3;
    const int lrow = lane & 7;
    uint32_t aOff[4], bOff[4];
#pragma unroll
    for (int mi=0;mi<4;mi++){
        int row = wm*64 + mi*16 + (m8 & 1)*8 + lrow;
        aOff[mi] = (uint32_t)(row*ROWB + (m8 >> 1)*16);
    }
#pragma unroll
    for (int pr=0;pr<4;pr++){
        int row = wn*64 + pr*16 + (m8 >> 1)*8 + lrow;
        bOff[pr] = (uint32_t)(A_BYTES + row*ROWB + (m8 & 1)*16);
    }

    float acc[4][8][4];
#pragma unroll
    for (int mi=0;mi<4;mi++)
#pragma unroll
        for(int ni=0;ni<8;ni++)
#pragma unroll
            for(int q=0;q<4;q++) acc[mi][ni][q]=0.f;

    for (int kt=0; kt<KT; kt++){
        __syncthreads();
        if (kt+1 < KT) issue(kt+1, (kt+1)&1);
        cp_commit();
        asm volatile("cp.async.wait_group 1;\n");
        __syncthreads();

        const uint32_t stAddr = sbase + (uint32_t)((kt&1)*STAGE_W)*4u;
#pragma unroll
        for (int k4=0; k4<8; k4++){
            const uint32_t kb = stAddr + (uint32_t)(k4*32);
            uint32_t a[4][4], b[8][2];
#pragma unroll
            for (int mi=0;mi<4;mi++)
                LDSM4(a[mi][0], a[mi][1], a[mi][2], a[mi][3], kb + aOff[mi]);
#pragma unroll
            for (int pr=0;pr<4;pr++)
                LDSM4(b[2*pr][0], b[2*pr][1], b[2*pr+1][0], b[2*pr+1][1], kb + bOff[pr]);
#pragma unroll
            for (int mi=0;mi<4;mi++)
#pragma unroll
                for (int ni=0;ni<8;ni++)
                    mma_f16(acc[mi][ni], a[mi][0],a[mi][1],a[mi][2],a[mi][3],
                            b[ni][0],b[ni][1]);
        }
    }
    asm volatile("cp.async.wait_group 0;\n");

    const int epiRow = mBase + wm*64 + gid;
    const int epiCol = nBase + wn*64 + t4*2;
#pragma unroll
    for (int mi=0;mi<4;mi++){
#pragma unroll
        for (int half=0; half<2; half++){
            int r = epiRow + mi*16 + half*8;
            size_t rowOff = (size_t)r*(size_t)LDE;
            float rsum = 0.f;
#pragma unroll
            for (int ni=0;ni<8;ni++){
                int col = epiCol + ni*8;
                float v0 = __expf(acc[mi][ni][half*2+0]);
                float v1 = __expf(acc[mi][ni][half*2+1]);
                if (col+1 < Ntot){
                    *(__half2*)(Cexp + rowOff + col) = __floats2half2_rn(v0, v1);
                    rsum += v0 + v1;
                } else if (col < Ntot){
                    Cexp[rowOff+col] = __float2half_rn(v0);
                    rsum += v0;
                }
            }
            rsum += __shfl_xor_sync(0xffffffffu, rsum, 1);
            rsum += __shfl_xor_sync(0xffffffffu, rsum, 2);
            if (t4 == 0) atomicAdd(&g_Z[r], rsum);
        }
    }
}

// ---------------- final: mixture + log (half2 reads) -------------------------
__global__ void final_kernel(float* __restrict__ out){
    int s = blockIdx.y;
    int v2 = blockIdx.x*256 + threadIdx.x;       // half2 index
    __shared__ float w[E_DIM];
    if (threadIdx.x < E_DIM){
        int idx = s*E_DIM + threadIdx.x;
        w[threadIdx.x] = g_gate[idx] / g_Z[idx];
    }
    __syncthreads();
    const int NV2 = V_DIM/2;
    if (v2 < NV2){
        const __half* base = g_expl + (size_t)(s*E_DIM)*LDE + 2*v2;
        float a0 = 0.f, a1 = 0.f;
#pragma unroll
        for (int e=0;e<E_DIM;e++){
            float2 p = __half22float2(*(const __half2*)(base + (size_t)e*LDE));
            a0 += w[e]*p.x; a1 += w[e]*p.y;
        }
        size_t o = (size_t)s*V_DIM + 2*v2;
        out[o]   = logf(a0 + 1e-10f);
        out[o+1] = logf(a1 + 1e-10f);
    } else if (v2 == NV2){
        const __half* base = g_expl + (size_t)(s*E_DIM)*LDE + (V_DIM-1);
        float a0 = 0.f;
#pragma unroll
        for (int e=0;e<E_DIM;e++) a0 += w[e]*__half2float(base[(size_t)e*LDE]);
        out[(size_t)s*V_DIM + (V_DIM-1)] = logf(a0 + 1e-10f);
    }
}

// ---------------- launch -----------------------------------------------------
extern "C" void kernel_launch(void* const* d_in, const int* in_sizes, int n_in,
                              void* d_out, int out_size){
    const float* hid  = (const float*)d_in[0];
    const float* emb  = (const float*)d_in[1];
    const float* nsc  = (const float*)d_in[2];
    const float* expw = (const float*)d_in[3];
    const float* gw   = (const float*)d_in[4];
    float* out = (float*)d_out;

    cudaFuncSetAttribute(gemm1_f16_kernel,
                         cudaFuncAttributeMaxDynamicSharedMemorySize, SMEM1_BYTES);
    cudaFuncSetAttribute(gemm2_f16_kernel,
                         cudaFuncAttributeMaxDynamicSharedMemorySize, SMEM2_BYTES);

    __half *phh, *pwh, *pehh, *pembh, *pexpl;
    cudaGetSymbolAddress((void**)&phh,   g_hh);
    cudaGetSymbolAddress((void**)&pwh,   g_wh);
    cudaGetSymbolAddress((void**)&pehh,  g_ehh);
    cudaGetSymbolAddress((void**)&pembh, g_embh);
    cudaGetSymbolAddress((void**)&pexpl, g_expl);

    // 1) rmsnorm + gate softmax + zero Z
    prep_kernel<<<S_DIM, 256>>>(hid, nsc, gw);

    // 2) embedding -> fp16 ; weights -> fp16 transposed [e][n][k]
    embconv_kernel<<<VPAD, 256>>>(emb);
    {
        dim3 g(H_DIM/32, H_DIM/32, E_DIM);   // (80, 80, 10)
        wconvT_kernel<<<g, 256>>>(expw);
    }

    // 3) expert_hidden (fp16 tensor cores, 2 CTA/SM); row r = s*E + e
    {
        dim3 g(S_DIM/T1M, H_DIM/T1N, E_DIM);   // (2, 20, 10) = 400 CTAs
        gemm1_f16_kernel<<<g, 256, SMEM1_BYTES>>>(phh, pwh, pehh);
    }

    // 4) exp(logits) fp16 tensor cores (f32 acc, TK=128, 2-stage, ldmatrix)
    {
        dim3 g(R_DIM/TM, (V_DIM + TN - 1)/TN, 1);   // (10, 393)
        gemm2_f16_kernel<<<g, 256, SMEM2_BYTES>>>(pehh, pembh, pexpl, V_DIM);
    }

    // 5) mixture + log
    {
        dim3 g((V_DIM/2 + 256)/256, S_DIM, 1);
        final_kernel<<<g, 256>>>(out);
    }
}